// round 2
// baseline (speedup 1.0000x reference)
#include <cuda_runtime.h>
#include <math_constants.h>

// Problem constants
#define HH   8
#define BB   16
#define GG   513
#define DD   256
#define DKC  32
#define EE   256
#define NPP  256
#define MROWS (BB*GG)            // 8208
#define PER  (HH*BB*GG*DKC)      // 2101248
#define NORMC 0.17677669529663687f
#define KSTRIDE 36               // smem row stride (floats): 16B-aligned, conflict-free

// Scratch (device globals; no allocation allowed)
__device__ float g_Q [PER];
__device__ float g_K [PER];
__device__ float g_V [PER];
__device__ float g_Q1[PER];
__device__ float g_Q2[PER];
__device__ float g_Q3[PER];
__device__ float g_Q4[PER];
__device__ float g_Q5[PER];
__device__ float g_Q6[PER];
__device__ float g_Hd[PER];

// ---------------------------------------------------------------------------
// Kernel A: projection GEMMs.  C[m][n] = sum_d X[m][d] * W[h][d][k], n=h*32+k
// Tile 128x64, K-chunk 16, 256 threads, 8x4 micro-tile per thread.
// blockIdx.z selects target 0..8.
// ---------------------------------------------------------------------------
__global__ __launch_bounds__(256) void proj_gemm(
    const float* __restrict__ qsrc, const float* __restrict__ hsrc,
    const float* __restrict__ Wq,  const float* __restrict__ Wk,
    const float* __restrict__ Wv,  const float* __restrict__ W1,
    const float* __restrict__ W2,  const float* __restrict__ W3,
    const float* __restrict__ W4,  const float* __restrict__ W5,
    const float* __restrict__ W6)
{
    const int t = blockIdx.z;
    const float* src = (t == 0) ? qsrc : hsrc;
    const float* W;
    float* outp;
    switch (t) {
        case 0: W = Wq; outp = g_Q;  break;
        case 1: W = Wk; outp = g_K;  break;
        case 2: W = Wv; outp = g_V;  break;
        case 3: W = W1; outp = g_Q1; break;
        case 4: W = W2; outp = g_Q2; break;
        case 5: W = W3; outp = g_Q3; break;
        case 6: W = W4; outp = g_Q4; break;
        case 7: W = W5; outp = g_Q5; break;
        default: W = W6; outp = g_Q6; break;
    }

    __shared__ float Ash[16][132];
    __shared__ float Bsh[16][68];

    const int tid = threadIdx.x;
    const int m0 = blockIdx.x * 128;
    const int n0 = blockIdx.y * 64;
    const int cx = tid & 15;     // 16 col-groups of 4
    const int ry = tid >> 4;     // 16 row-groups

    float acc[8][4];
#pragma unroll
    for (int i = 0; i < 8; i++)
#pragma unroll
        for (int j = 0; j < 4; j++) acc[i][j] = 0.f;

    for (int d0 = 0; d0 < 256; d0 += 16) {
        // Load A tile: 128 rows x 16 d (transposed into Ash[d][row])
#pragma unroll
        for (int i = 0; i < 2; i++) {
            int fid = tid + i * 256;
            int row = fid >> 2;
            int dg  = (fid & 3) * 4;
            int m   = m0 + row;
            float4 v = make_float4(0.f, 0.f, 0.f, 0.f);
            if (m < MROWS)
                v = *(const float4*)(src + (size_t)m * 256 + d0 + dg);
            Ash[dg + 0][row] = v.x;
            Ash[dg + 1][row] = v.y;
            Ash[dg + 2][row] = v.z;
            Ash[dg + 3][row] = v.w;
        }
        // Load B tile: 16 d x 64 n  (W is [h][d][k], n=h*32+k)
        {
            int d  = tid >> 4;
            int nn = (tid & 15) * 4;
            int n  = n0 + nn;
            float4 v = *(const float4*)(W + (size_t)(n >> 5) * 8192 +
                                        (size_t)(d0 + d) * 32 + (n & 31));
            *(float4*)&Bsh[d][nn] = v;
        }
        __syncthreads();

#pragma unroll
        for (int d = 0; d < 16; d++) {
            float4 a0 = *(const float4*)&Ash[d][ry * 4];
            float4 a1 = *(const float4*)&Ash[d][64 + ry * 4];
            float4 bv = *(const float4*)&Bsh[d][cx * 4];
            float ar[8] = {a0.x, a0.y, a0.z, a0.w, a1.x, a1.y, a1.z, a1.w};
            float br[4] = {bv.x, bv.y, bv.z, bv.w};
#pragma unroll
            for (int i = 0; i < 8; i++)
#pragma unroll
                for (int j = 0; j < 4; j++)
                    acc[i][j] = fmaf(ar[i], br[j], acc[i][j]);
        }
        __syncthreads();
    }

#pragma unroll
    for (int i = 0; i < 8; i++) {
        int row = (i < 4) ? (ry * 4 + i) : (64 + ry * 4 + (i - 4));
        int m = m0 + row;
        if (m >= MROWS) continue;
        int bb = m / GG, node = m % GG;
#pragma unroll
        for (int j = 0; j < 4; j++) {
            int n = n0 + cx * 4 + j;
            int hh = n >> 5, kk = n & 31;
            outp[(((size_t)hh * BB + bb) * GG + node) * DKC + kk] = acc[i][j];
        }
    }
}

// ---------------------------------------------------------------------------
// Kernel B: fused attention. One block per (b,h); K/V resident in smem
// (stride 36: float4-aligned, conflict-free); warp-per-query; logits in
// registers; single-pass weighted-V accumulation with shuffle-broadcast.
// ---------------------------------------------------------------------------
__device__ __forceinline__ float warpMaxf(float v) {
#pragma unroll
    for (int o = 16; o; o >>= 1) v = fmaxf(v, __shfl_xor_sync(0xffffffffu, v, o));
    return v;
}
__device__ __forceinline__ float warpSumf(float v) {
#pragma unroll
    for (int o = 16; o; o >>= 1) v += __shfl_xor_sync(0xffffffffu, v, o);
    return v;
}

__global__ __launch_bounds__(256, 1) void attn_kernel()
{
    extern __shared__ float smem[];
    float* Ksh = smem;                   // [513][36]
    float* Vsh = smem + GG * KSTRIDE;    // [513][36]

    const int b  = blockIdx.x;
    const int hh = blockIdx.y;
    const int tid = threadIdx.x, lane = tid & 31, wid = tid >> 5;
    const size_t base = (((size_t)hh * BB + b) * GG) * DKC;

    for (int i = tid; i < GG * DKC; i += 256) {
        int m = i >> 5, k = i & 31;
        Ksh[m * KSTRIDE + k] = g_K[base + i];
        Vsh[m * KSTRIDE + k] = g_V[base + i];
    }
    __syncthreads();

    for (int n = wid; n < GG; n += 8) {
        const bool isPick = (n >= 1 && n <= NPP);
        float t0 = g_Q[base + (size_t)n * DKC + lane];
        float t1 = 0.f, t2 = 0.f, ta = 0.f;
        int pair = 0;
        if (n >= 1) {
            const float* U1p = isPick ? (g_Q2 + base) : (g_Q6 + base);  // keys 1..256
            const float* U2p = isPick ? (g_Q3 + base) : (g_Q5 + base);  // keys 257..512
            const float* QAp = isPick ? (g_Q1 + base) : (g_Q4 + base);  // pair
            t1 = U1p[(size_t)n * DKC + lane];
            t2 = U2p[(size_t)n * DKC + lane];
            ta = QAp[(size_t)n * DKC + lane];
            pair = isPick ? n + NPP : n - NPP;
        }
        float qb[32], u1[32], u2[32];
#pragma unroll
        for (int k = 0; k < 32; k++) {
            qb[k] = __shfl_sync(0xffffffffu, t0, k);
            u1[k] = __shfl_sync(0xffffffffu, t1, k);
            u2[k] = __shfl_sync(0xffffffffu, t2, k);
        }

        // depot (m=0) base logit + pair logit via warp reductions
        float l00 = NORMC * warpSumf(t0 * Ksh[lane]);
        float lpair = -CUDART_INF_F;
        if (n >= 1) lpair = NORMC * warpSumf(ta * Ksh[pair * KSTRIDE + lane]);

        // main logit pass: lane handles node m1=1+jb*32+lane (pick half) and
        // m2=257+jb*32+lane (delivery half): base dot + extra dot each.
        // K rows read as float4 (LDS.128): 1 load per 16 FFMA.
        float l0a[8], l1a[8], l0b[8], l1b[8];
#pragma unroll
        for (int jb = 0; jb < 8; jb++) {
            const float4* kr1 = (const float4*)&Ksh[(1   + jb * 32 + lane) * KSTRIDE];
            const float4* kr2 = (const float4*)&Ksh[(257 + jb * 32 + lane) * KSTRIDE];
            float a0 = 0.f, a1 = 0.f, b0 = 0.f, b1 = 0.f;
#pragma unroll
            for (int k4 = 0; k4 < 8; k4++) {
                float4 kv1 = kr1[k4];
                float4 kv2 = kr2[k4];
                int k = k4 * 4;
                a0 = fmaf(qb[k+0], kv1.x, a0); a0 = fmaf(qb[k+1], kv1.y, a0);
                a0 = fmaf(qb[k+2], kv1.z, a0); a0 = fmaf(qb[k+3], kv1.w, a0);
                a1 = fmaf(u1[k+0], kv1.x, a1); a1 = fmaf(u1[k+1], kv1.y, a1);
                a1 = fmaf(u1[k+2], kv1.z, a1); a1 = fmaf(u1[k+3], kv1.w, a1);
                b0 = fmaf(qb[k+0], kv2.x, b0); b0 = fmaf(qb[k+1], kv2.y, b0);
                b0 = fmaf(qb[k+2], kv2.z, b0); b0 = fmaf(qb[k+3], kv2.w, b0);
                b1 = fmaf(u2[k+0], kv2.x, b1); b1 = fmaf(u2[k+1], kv2.y, b1);
                b1 = fmaf(u2[k+2], kv2.z, b1); b1 = fmaf(u2[k+3], kv2.w, b1);
            }
            l0a[jb] = a0 * NORMC; l1a[jb] = a1 * NORMC;
            l0b[jb] = b0 * NORMC; l1b[jb] = b1 * NORMC;
        }

        // softmax max
        float mx = l00;
        if (n >= 1) mx = fmaxf(mx, lpair);
#pragma unroll
        for (int jb = 0; jb < 8; jb++) {
            mx = fmaxf(mx, l0a[jb]);
            mx = fmaxf(mx, l0b[jb]);
            if (n >= 1) { mx = fmaxf(mx, l1a[jb]); mx = fmaxf(mx, l1b[jb]); }
        }
        mx = warpMaxf(mx);

        float ep  = (n >= 1) ? __expf(lpair - mx) : 0.f;
        float e00 = __expf(l00 - mx);

        int jt = -1, lt = 0; bool pairInA = false;
        if (n >= 1) {
            int j = isPick ? (n - 1) : (n - NPP - 1);
            jt = j >> 5; lt = j & 31;
            pairInA = !isPick;     // delivery query -> pair node in 1..256 half
        }

        float wa[8], wb[8];
        float part = 0.f;
#pragma unroll
        for (int jb = 0; jb < 8; jb++) {
            float ea = __expf(l0a[jb] - mx);
            float eb = __expf(l0b[jb] - mx);
            if (n >= 1) {
                ea += __expf(l1a[jb] - mx);
                eb += __expf(l1b[jb] - mx);
            }
            if (jb == jt && lane == lt) {
                if (pairInA) ea += ep; else eb += ep;
            }
            wa[jb] = ea; wb[jb] = eb;
            part += ea + eb;
        }
        float tot = warpSumf(part) + e00;   // ep already folded into its w slot
        float inv = 1.0f / tot;

        // weighted V accumulation: heads[lane] = sum_m w[m] * V[m][lane]
        float accv = e00 * Vsh[lane];
#pragma unroll
        for (int jb = 0; jb < 8; jb++) {
#pragma unroll 8
            for (int tt = 0; tt < 32; tt++) {
                float w1 = __shfl_sync(0xffffffffu, wa[jb], tt);
                float w2 = __shfl_sync(0xffffffffu, wb[jb], tt);
                accv = fmaf(w1, Vsh[(1   + jb * 32 + tt) * KSTRIDE + lane], accv);
                accv = fmaf(w2, Vsh[(257 + jb * 32 + tt) * KSTRIDE + lane], accv);
            }
        }
        g_Hd[base + (size_t)n * DKC + lane] = accv * inv;
    }
}

// ---------------------------------------------------------------------------
// Kernel C: output projection. out[m][e] = sum_c heads[m][c] * Wout[c][e]
// where c = h*32+k, heads gathered from g_Hd, Wout[(h,k),e] contiguous.
// ---------------------------------------------------------------------------
__global__ __launch_bounds__(256) void out_gemm(
    const float* __restrict__ Wout, float* __restrict__ out)
{
    __shared__ float Ash[16][132];
    __shared__ float Bsh[16][68];

    const int tid = threadIdx.x;
    const int m0 = blockIdx.x * 128;
    const int n0 = blockIdx.y * 64;
    const int cx = tid & 15;
    const int ry = tid >> 4;

    float acc[8][4];
#pragma unroll
    for (int i = 0; i < 8; i++)
#pragma unroll
        for (int j = 0; j < 4; j++) acc[i][j] = 0.f;

    for (int d0 = 0; d0 < 256; d0 += 16) {
#pragma unroll
        for (int i = 0; i < 2; i++) {
            int fid = tid + i * 256;
            int row = fid >> 2;
            int cg  = (fid & 3) * 4;
            int m   = m0 + row;
            int c   = d0 + cg;
            float4 v = make_float4(0.f, 0.f, 0.f, 0.f);
            if (m < MROWS)
                v = *(const float4*)(g_Hd + (size_t)(c >> 5) * MROWS * DKC +
                                     (size_t)m * DKC + (c & 31));
            Ash[cg + 0][row] = v.x;
            Ash[cg + 1][row] = v.y;
            Ash[cg + 2][row] = v.z;
            Ash[cg + 3][row] = v.w;
        }
        {
            int d  = tid >> 4;
            int nn = (tid & 15) * 4;
            float4 v = *(const float4*)(Wout + (size_t)(d0 + d) * EE + n0 + nn);
            *(float4*)&Bsh[d][nn] = v;
        }
        __syncthreads();

#pragma unroll
        for (int d = 0; d < 16; d++) {
            float4 a0 = *(const float4*)&Ash[d][ry * 4];
            float4 a1 = *(const float4*)&Ash[d][64 + ry * 4];
            float4 bv = *(const float4*)&Bsh[d][cx * 4];
            float ar[8] = {a0.x, a0.y, a0.z, a0.w, a1.x, a1.y, a1.z, a1.w};
            float br[4] = {bv.x, bv.y, bv.z, bv.w};
#pragma unroll
            for (int i = 0; i < 8; i++)
#pragma unroll
                for (int j = 0; j < 4; j++)
                    acc[i][j] = fmaf(ar[i], br[j], acc[i][j]);
        }
        __syncthreads();
    }

#pragma unroll
    for (int i = 0; i < 8; i++) {
        int row = (i < 4) ? (ry * 4 + i) : (64 + ry * 4 + (i - 4));
        int m = m0 + row;
        if (m >= MROWS) continue;
#pragma unroll
        for (int j = 0; j < 4; j++) {
            out[(size_t)m * EE + n0 + cx * 4 + j] = acc[i][j];
        }
    }
}

// ---------------------------------------------------------------------------
extern "C" void kernel_launch(void* const* d_in, const int* in_sizes, int n_in,
                              void* d_out, int out_size)
{
    (void)in_sizes; (void)n_in; (void)out_size;
    const float* q    = (const float*)d_in[0];
    const float* h    = (const float*)d_in[1];
    const float* Wq   = (const float*)d_in[2];
    const float* Wk   = (const float*)d_in[3];
    const float* Wv   = (const float*)d_in[4];
    const float* W1   = (const float*)d_in[5];
    const float* W2   = (const float*)d_in[6];
    const float* W3   = (const float*)d_in[7];
    const float* W4   = (const float*)d_in[8];
    const float* W5   = (const float*)d_in[9];
    const float* W6   = (const float*)d_in[10];
    const float* Wout = (const float*)d_in[11];
    float* out = (float*)d_out;

    const int SMEM_ATTN = 2 * GG * KSTRIDE * (int)sizeof(float);  // 147744 B
    cudaFuncSetAttribute(attn_kernel,
                         cudaFuncAttributeMaxDynamicSharedMemorySize, SMEM_ATTN);

    dim3 gridP((MROWS + 127) / 128, 4, 9);     // 65 x 4 x 9
    proj_gemm<<<gridP, 256>>>(q, h, Wq, Wk, Wv, W1, W2, W3, W4, W5, W6);

    dim3 gridA(BB, HH);                        // 16 x 8
    attn_kernel<<<gridA, 256, SMEM_ATTN>>>();

    dim3 gridO((MROWS + 127) / 128, 4);        // 65 x 4
    out_gemm<<<gridO, 256>>>(Wout, out);
}

// round 6
// speedup vs baseline: 1.1472x; 1.1472x over previous
#include <cuda_runtime.h>
#include <math_constants.h>

// Problem constants
#define HH   8
#define BB   16
#define GG   513
#define DD   256
#define DKC  32
#define EE   256
#define NPP  256
#define MROWS (BB*GG)            // 8208
#define PER  (HH*BB*GG*DKC)      // 2101248
#define NORMC 0.17677669529663687f

// attn smem layout (float offsets)
#define PADM 516                 // Kt/Vt row pad (516 % 32 == 4 -> conflict-free f4)
#define LPAD 520                 // logit/weight row pad
#define OFF_KT  0                // Kt[32][516]
#define OFF_VT  16512            // Vt[32][516]
#define OFF_L0  33024            // L0b[16][520] (raw base logits -> combined weights)
#define OFF_LX  41344            // Lxb[16][520] (raw extra logits -> AV partials)
#define OFF_QB  49664            // qb [16][32]
#define OFF_U1  50176
#define OFF_U2  50688
#define OFF_QA  51200
#define OFF_TOT 51712            // invtot[16]
#define SMEM_FLOATS 51728        // 206912 bytes

// Scratch (device globals; no allocation allowed)
__device__ float g_Q [PER];
__device__ float g_K [PER];
__device__ float g_V [PER];
__device__ float g_Q1[PER];
__device__ float g_Q2[PER];
__device__ float g_Q3[PER];
__device__ float g_Q4[PER];
__device__ float g_Q5[PER];
__device__ float g_Q6[PER];
__device__ float g_Hd[PER];

// ---------------------------------------------------------------------------
// Kernel A: projection GEMMs (unchanged from R2 passing version)
// ---------------------------------------------------------------------------
__global__ __launch_bounds__(256) void proj_gemm(
    const float* __restrict__ qsrc, const float* __restrict__ hsrc,
    const float* __restrict__ Wq,  const float* __restrict__ Wk,
    const float* __restrict__ Wv,  const float* __restrict__ W1,
    const float* __restrict__ W2,  const float* __restrict__ W3,
    const float* __restrict__ W4,  const float* __restrict__ W5,
    const float* __restrict__ W6)
{
    const int t = blockIdx.z;
    const float* src = (t == 0) ? qsrc : hsrc;
    const float* W;
    float* outp;
    switch (t) {
        case 0: W = Wq; outp = g_Q;  break;
        case 1: W = Wk; outp = g_K;  break;
        case 2: W = Wv; outp = g_V;  break;
        case 3: W = W1; outp = g_Q1; break;
        case 4: W = W2; outp = g_Q2; break;
        case 5: W = W3; outp = g_Q3; break;
        case 6: W = W4; outp = g_Q4; break;
        case 7: W = W5; outp = g_Q5; break;
        default: W = W6; outp = g_Q6; break;
    }

    __shared__ float Ash[16][132];
    __shared__ float Bsh[16][68];

    const int tid = threadIdx.x;
    const int m0 = blockIdx.x * 128;
    const int n0 = blockIdx.y * 64;
    const int cx = tid & 15;
    const int ry = tid >> 4;

    float acc[8][4];
#pragma unroll
    for (int i = 0; i < 8; i++)
#pragma unroll
        for (int j = 0; j < 4; j++) acc[i][j] = 0.f;

    for (int d0 = 0; d0 < 256; d0 += 16) {
#pragma unroll
        for (int i = 0; i < 2; i++) {
            int fid = tid + i * 256;
            int row = fid >> 2;
            int dg  = (fid & 3) * 4;
            int m   = m0 + row;
            float4 v = make_float4(0.f, 0.f, 0.f, 0.f);
            if (m < MROWS)
                v = *(const float4*)(src + (size_t)m * 256 + d0 + dg);
            Ash[dg + 0][row] = v.x;
            Ash[dg + 1][row] = v.y;
            Ash[dg + 2][row] = v.z;
            Ash[dg + 3][row] = v.w;
        }
        {
            int d  = tid >> 4;
            int nn = (tid & 15) * 4;
            int n  = n0 + nn;
            float4 v = *(const float4*)(W + (size_t)(n >> 5) * 8192 +
                                        (size_t)(d0 + d) * 32 + (n & 31));
            *(float4*)&Bsh[d][nn] = v;
        }
        __syncthreads();

#pragma unroll
        for (int d = 0; d < 16; d++) {
            float4 a0 = *(const float4*)&Ash[d][ry * 4];
            float4 a1 = *(const float4*)&Ash[d][64 + ry * 4];
            float4 bv = *(const float4*)&Bsh[d][cx * 4];
            float ar[8] = {a0.x, a0.y, a0.z, a0.w, a1.x, a1.y, a1.z, a1.w};
            float br[4] = {bv.x, bv.y, bv.z, bv.w};
#pragma unroll
            for (int i = 0; i < 8; i++)
#pragma unroll
                for (int j = 0; j < 4; j++)
                    acc[i][j] = fmaf(ar[i], br[j], acc[i][j]);
        }
        __syncthreads();
    }

#pragma unroll
    for (int i = 0; i < 8; i++) {
        int row = (i < 4) ? (ry * 4 + i) : (64 + ry * 4 + (i - 4));
        int m = m0 + row;
        if (m >= MROWS) continue;
        int bb = m / GG, node = m % GG;
#pragma unroll
        for (int j = 0; j < 4; j++) {
            int n = n0 + cx * 4 + j;
            int hh = n >> 5, kk = n & 31;
            outp[(((size_t)hh * BB + bb) * GG + node) * DKC + kk] = acc[i][j];
        }
    }
}

// ---------------------------------------------------------------------------
// Kernel B: fused attention, chunked-GEMM formulation.
// One CTA per (b,h); K,V transposed & resident in smem; 16-query chunks:
//   P2: logit GEMM (4q x 8m register tiles) -> raw logits in smem
//   P3: softmax (warp per 2 queries), combined weights in place
//   P4: AV GEMM (warp per 64-key slice, 16 accumulators) + reduce
// ---------------------------------------------------------------------------
__device__ __forceinline__ float warpMaxf(float v) {
#pragma unroll
    for (int o = 16; o; o >>= 1) v = fmaxf(v, __shfl_xor_sync(0xffffffffu, v, o));
    return v;
}
__device__ __forceinline__ float warpSumf(float v) {
#pragma unroll
    for (int o = 16; o; o >>= 1) v += __shfl_xor_sync(0xffffffffu, v, o);
    return v;
}

__global__ __launch_bounds__(256, 1) void attn_kernel()
{
    extern __shared__ float sm[];
    float* Kt  = sm + OFF_KT;
    float* Vt  = sm + OFF_VT;
    float* L0b = sm + OFF_L0;
    float* Lxb = sm + OFF_LX;

    const int b  = blockIdx.x;
    const int hh = blockIdx.y;
    const int tid = threadIdx.x, lane = tid & 31, wid = tid >> 5;
    const size_t base = (((size_t)hh * BB + b) * GG) * DKC;
    const float NINF = -CUDART_INF_F;

    // zero pad columns 513..515 (needed by AV sweep of warp 7)
    if (tid < 96) {
        int k = tid / 3, cc = 513 + (tid - k * 3);
        Kt[k * PADM + cc] = 0.f;
        Vt[k * PADM + cc] = 0.f;
    }
    // load K/V transposed: Kt[k][m], Vt[k][m]
    for (int i = tid; i < GG * DKC; i += 256) {
        int m = i >> 5, k = i & 31;
        float kv = g_K[base + i];
        float vv = g_V[base + i];
        Kt[k * PADM + m] = kv;
        Vt[k * PADM + m] = vv;
    }
    __syncthreads();

    for (int c = 0; c < 33; c++) {
        const int q0 = c * 16;

        // ---- Phase 1: stage query vectors for this chunk ----
        for (int i = tid; i < 2048; i += 256) {
            int type = i >> 9, qq = (i >> 5) & 15, k = i & 31;
            int n = q0 + qq;
            float v = 0.f;
            if (n < GG) {
                size_t off = base + (size_t)n * 32 + k;
                bool pick = (n >= 1 && n <= NPP);
                if (type == 0)          v = g_Q[off];
                else if (n >= 1) {
                    if (type == 1)      v = pick ? g_Q2[off] : g_Q6[off];
                    else if (type == 2) v = pick ? g_Q3[off] : g_Q5[off];
                    else                v = pick ? g_Q1[off] : g_Q4[off];
                }
            }
            sm[OFF_QB + i] = v;   // QB,U1,U2,QA are contiguous 512-blocks
        }
        __syncthreads();

        // ---- Phase 2: logit GEMM ----
        {
            const int qg = tid >> 6;          // 0..3 (4 queries each)
            const int mt = tid & 63;          // 64 m-threads
            const int mA = mt * 4;            // keys 0..255
            const int mB = 256 + mt * 4;      // keys 256..511
            float L0r[4][8], Lxr[4][8];
#pragma unroll
            for (int qq = 0; qq < 4; qq++)
#pragma unroll
                for (int j = 0; j < 8; j++) { L0r[qq][j] = 0.f; Lxr[qq][j] = 0.f; }

            const int qbase = (qg * 4) * 32;
            for (int k = 0; k < 32; k++) {
                float4 ka = *(const float4*)&Kt[k * PADM + mA];
                float4 kb = *(const float4*)&Kt[k * PADM + mB];
#pragma unroll
                for (int qq = 0; qq < 4; qq++) {
                    int qi = qbase + qq * 32 + k;
                    float qv  = sm[OFF_QB + qi];
                    float u1v = sm[OFF_U1 + qi];
                    float u2v = sm[OFF_U2 + qi];
                    L0r[qq][0] = fmaf(qv, ka.x, L0r[qq][0]);
                    L0r[qq][1] = fmaf(qv, ka.y, L0r[qq][1]);
                    L0r[qq][2] = fmaf(qv, ka.z, L0r[qq][2]);
                    L0r[qq][3] = fmaf(qv, ka.w, L0r[qq][3]);
                    L0r[qq][4] = fmaf(qv, kb.x, L0r[qq][4]);
                    L0r[qq][5] = fmaf(qv, kb.y, L0r[qq][5]);
                    L0r[qq][6] = fmaf(qv, kb.z, L0r[qq][6]);
                    L0r[qq][7] = fmaf(qv, kb.w, L0r[qq][7]);
                    Lxr[qq][0] = fmaf(u1v, ka.x, Lxr[qq][0]);
                    Lxr[qq][1] = fmaf(u1v, ka.y, Lxr[qq][1]);
                    Lxr[qq][2] = fmaf(u1v, ka.z, Lxr[qq][2]);
                    Lxr[qq][3] = fmaf(u1v, ka.w, Lxr[qq][3]);
                    Lxr[qq][4] = fmaf(u2v, kb.x, Lxr[qq][4]);
                    Lxr[qq][5] = fmaf(u2v, kb.y, Lxr[qq][5]);
                    Lxr[qq][6] = fmaf(u2v, kb.z, Lxr[qq][6]);
                    Lxr[qq][7] = fmaf(u2v, kb.w, Lxr[qq][7]);
                    if (mt == 0)   // m==256 is a pick key: uses u1, not u2
                        Lxr[qq][4] = fmaf(u1v - u2v, kb.x, Lxr[qq][4]);
                }
            }
#pragma unroll
            for (int qq = 0; qq < 4; qq++) {
                int q = qg * 4 + qq;
                if (mt == 0) Lxr[qq][0] = NINF;   // m==0: no extra logit
                float4 oa = make_float4(L0r[qq][0]*NORMC, L0r[qq][1]*NORMC,
                                        L0r[qq][2]*NORMC, L0r[qq][3]*NORMC);
                float4 ob = make_float4(L0r[qq][4]*NORMC, L0r[qq][5]*NORMC,
                                        L0r[qq][6]*NORMC, L0r[qq][7]*NORMC);
                *(float4*)&L0b[q * LPAD + mA] = oa;
                *(float4*)&L0b[q * LPAD + mB] = ob;
                float4 xa = make_float4(Lxr[qq][0]*NORMC, Lxr[qq][1]*NORMC,
                                        Lxr[qq][2]*NORMC, Lxr[qq][3]*NORMC);
                float4 xb = make_float4(Lxr[qq][4]*NORMC, Lxr[qq][5]*NORMC,
                                        Lxr[qq][6]*NORMC, Lxr[qq][7]*NORMC);
                *(float4*)&Lxb[q * LPAD + mA] = xa;
                *(float4*)&Lxb[q * LPAD + mB] = xb;
            }
        }
        __syncthreads();

        // ---- Phase 3: softmax (warp handles 2 queries) ----
        for (int s = 0; s < 2; s++) {
            int qq = wid * 2 + s;
            int n = q0 + qq;
            float* wrow = &L0b[qq * LPAD];
            float* xrow = &Lxb[qq * LPAD];
            if (n < GG) {
                const bool useX = (n >= 1);
                // special logits: key 512 (base + extra) and pair
                float kv512 = Kt[lane * PADM + 512];
                float l0_512 = NORMC * warpSumf(sm[OFF_QB + qq*32 + lane] * kv512);
                float lx512 = NINF, lp = NINF;
                int p = 0;
                if (useX) {
                    lx512 = NORMC * warpSumf(sm[OFF_U2 + qq*32 + lane] * kv512);
                    p = (n <= NPP) ? n + NPP : n - NPP;
                    float kvp = Kt[lane * PADM + p];
                    lp = NORMC * warpSumf(sm[OFF_QA + qq*32 + lane] * kvp);
                }
                // row max
                float mx = fmaxf(l0_512, fmaxf(lx512, lp));
#pragma unroll
                for (int i = 0; i < 4; i++) {
                    int m4 = i * 128 + lane * 4;
                    float4 a = *(const float4*)&wrow[m4];
                    mx = fmaxf(mx, fmaxf(fmaxf(a.x, a.y), fmaxf(a.z, a.w)));
                    if (useX) {
                        float4 x = *(const float4*)&xrow[m4];
                        mx = fmaxf(mx, fmaxf(fmaxf(x.x, x.y), fmaxf(x.z, x.w)));
                    }
                }
                mx = warpMaxf(mx);
                // exp + combine, write weights in place
                float tot = 0.f;
#pragma unroll
                for (int i = 0; i < 4; i++) {
                    int m4 = i * 128 + lane * 4;
                    float4 a = *(const float4*)&wrow[m4];
                    float4 wv;
                    wv.x = __expf(a.x - mx); wv.y = __expf(a.y - mx);
                    wv.z = __expf(a.z - mx); wv.w = __expf(a.w - mx);
                    if (useX) {
                        float4 x = *(const float4*)&xrow[m4];
                        wv.x += __expf(x.x - mx); wv.y += __expf(x.y - mx);
                        wv.z += __expf(x.z - mx); wv.w += __expf(x.w - mx);
                    }
                    tot += wv.x + wv.y + wv.z + wv.w;
                    *(float4*)&wrow[m4] = wv;
                }
                tot = warpSumf(tot);
                float w512 = __expf(l0_512 - mx) + (useX ? __expf(lx512 - mx) : 0.f);
                float wp   = useX ? __expf(lp - mx) : 0.f;
                tot += w512 + wp;
                __syncwarp();
                if (lane == 0) {
                    wrow[512] = w512;
                    if (useX) wrow[p] += wp;
                    wrow[513] = 0.f; wrow[514] = 0.f; wrow[515] = 0.f;
                    sm[OFF_TOT + qq] = 1.0f / tot;
                }
            } else {
                for (int i = lane; i < 129; i += 32)
                    *(float4*)&wrow[i * 4] = make_float4(0.f, 0.f, 0.f, 0.f);
                if (lane == 0) sm[OFF_TOT + qq] = 0.f;
            }
        }
        __syncthreads();

        // ---- Phase 4: AV GEMM (warp per 64-key slice) ----
        {
            float acc[16];
#pragma unroll
            for (int qq = 0; qq < 16; qq++) acc[qq] = 0.f;
            const int iters = (wid == 7) ? 17 : 16;
            const int mbase = wid * 64;
            for (int it = 0; it < iters; it++) {
                int m4 = mbase + it * 4;
                float4 v = *(const float4*)&Vt[lane * PADM + m4];
#pragma unroll
                for (int qq = 0; qq < 16; qq++) {
                    float4 wv = *(const float4*)&L0b[qq * LPAD + m4];
                    acc[qq] = fmaf(wv.x, v.x, acc[qq]);
                    acc[qq] = fmaf(wv.y, v.y, acc[qq]);
                    acc[qq] = fmaf(wv.z, v.z, acc[qq]);
                    acc[qq] = fmaf(wv.w, v.w, acc[qq]);
                }
            }
            // stage partials into Lxb (free after softmax)
#pragma unroll
            for (int qq = 0; qq < 16; qq++)
                Lxb[(wid * 16 + qq) * 32 + lane] = acc[qq];
        }
        __syncthreads();

        // ---- Phase 5: reduce partials + writeout ----
        for (int o = tid; o < 512; o += 256) {
            int qq = o >> 5, k = o & 31;
            float s = 0.f;
#pragma unroll
            for (int w = 0; w < 8; w++)
                s += Lxb[(w * 16 + qq) * 32 + k];
            int n = q0 + qq;
            if (n < GG)
                g_Hd[base + (size_t)n * 32 + k] = s * sm[OFF_TOT + qq];
        }
        __syncthreads();
    }
}

// ---------------------------------------------------------------------------
// Kernel C: output projection (unchanged)
// ---------------------------------------------------------------------------
__global__ __launch_bounds__(256) void out_gemm(
    const float* __restrict__ Wout, float* __restrict__ out)
{
    __shared__ float Ash[16][132];
    __shared__ float Bsh[16][68];

    const int tid = threadIdx.x;
    const int m0 = blockIdx.x * 128;
    const int n0 = blockIdx.y * 64;
    const int cx = tid & 15;
    const int ry = tid >> 4;

    float acc[8][4];
#pragma unroll
    for (int i = 0; i < 8; i++)
#pragma unroll
        for (int j = 0; j < 4; j++) acc[i][j] = 0.f;

    for (int d0 = 0; d0 < 256; d0 += 16) {
#pragma unroll
        for (int i = 0; i < 2; i++) {
            int fid = tid + i * 256;
            int row = fid >> 2;
            int cg  = (fid & 3) * 4;
            int m   = m0 + row;
            int cc  = d0 + cg;
            float4 v = make_float4(0.f, 0.f, 0.f, 0.f);
            if (m < MROWS)
                v = *(const float4*)(g_Hd + (size_t)(cc >> 5) * MROWS * DKC +
                                     (size_t)m * DKC + (cc & 31));
            Ash[cg + 0][row] = v.x;
            Ash[cg + 1][row] = v.y;
            Ash[cg + 2][row] = v.z;
            Ash[cg + 3][row] = v.w;
        }
        {
            int d  = tid >> 4;
            int nn = (tid & 15) * 4;
            float4 v = *(const float4*)(Wout + (size_t)(d0 + d) * EE + n0 + nn);
            *(float4*)&Bsh[d][nn] = v;
        }
        __syncthreads();

#pragma unroll
        for (int d = 0; d < 16; d++) {
            float4 a0 = *(const float4*)&Ash[d][ry * 4];
            float4 a1 = *(const float4*)&Ash[d][64 + ry * 4];
            float4 bv = *(const float4*)&Bsh[d][cx * 4];
            float ar[8] = {a0.x, a0.y, a0.z, a0.w, a1.x, a1.y, a1.z, a1.w};
            float br[4] = {bv.x, bv.y, bv.z, bv.w};
#pragma unroll
            for (int i = 0; i < 8; i++)
#pragma unroll
                for (int j = 0; j < 4; j++)
                    acc[i][j] = fmaf(ar[i], br[j], acc[i][j]);
        }
        __syncthreads();
    }

#pragma unroll
    for (int i = 0; i < 8; i++) {
        int row = (i < 4) ? (ry * 4 + i) : (64 + ry * 4 + (i - 4));
        int m = m0 + row;
        if (m >= MROWS) continue;
#pragma unroll
        for (int j = 0; j < 4; j++) {
            out[(size_t)m * EE + n0 + cx * 4 + j] = acc[i][j];
        }
    }
}

// ---------------------------------------------------------------------------
extern "C" void kernel_launch(void* const* d_in, const int* in_sizes, int n_in,
                              void* d_out, int out_size)
{
    (void)in_sizes; (void)n_in; (void)out_size;
    const float* q    = (const float*)d_in[0];
    const float* h    = (const float*)d_in[1];
    const float* Wq   = (const float*)d_in[2];
    const float* Wk   = (const float*)d_in[3];
    const float* Wv   = (const float*)d_in[4];
    const float* W1   = (const float*)d_in[5];
    const float* W2   = (const float*)d_in[6];
    const float* W3   = (const float*)d_in[7];
    const float* W4   = (const float*)d_in[8];
    const float* W5   = (const float*)d_in[9];
    const float* W6   = (const float*)d_in[10];
    const float* Wout = (const float*)d_in[11];
    float* out = (float*)d_out;

    const int SMEM_ATTN = SMEM_FLOATS * (int)sizeof(float);  // 206912 B
    cudaFuncSetAttribute(attn_kernel,
                         cudaFuncAttributeMaxDynamicSharedMemorySize, SMEM_ATTN);

    dim3 gridP((MROWS + 127) / 128, 4, 9);     // 65 x 4 x 9
    proj_gemm<<<gridP, 256>>>(q, h, Wq, Wk, Wv, W1, W2, W3, W4, W5, W6);

    dim3 gridA(BB, HH);                        // 16 x 8
    attn_kernel<<<gridA, 256, SMEM_ATTN>>>();

    dim3 gridO((MROWS + 127) / 128, 4);        // 65 x 4
    out_gemm<<<gridO, 256>>>(Wout, out);
}

// round 8
// speedup vs baseline: 1.3740x; 1.1977x over previous
#include <cuda_runtime.h>
#include <math_constants.h>

// Problem constants
#define HH   8
#define BB   16
#define GG   513
#define DD   256
#define DKC  32
#define EE   256
#define NPP  256
#define MROWS (BB*GG)            // 8208
#define PER  (HH*BB*GG*DKC)      // 2101248
#define NORMC 0.17677669529663687f

// attn smem layout (float offsets)
#define PADM 516                 // Kt/Vt row pad (516 % 32 == 4 -> conflict-free f4)
#define LPAD 520                 // logit/weight row pad
#define OFF_KT  0                // Kt[32][516]
#define OFF_VT  16512            // Vt[32][516]
#define OFF_L0  33024            // L0b[16][520] (raw base logits -> combined weights)
#define OFF_LX  41344            // Lxb[16][520] (raw extra logits -> AV partials)
#define OFF_QB  49664            // qb [16][32]
#define OFF_U1  50176
#define OFF_U2  50688
#define OFF_QA  51200
#define OFF_TOT 51712            // invtot[16]
#define SMEM_FLOATS 51728        // 206912 bytes

// Scratch (device globals; no allocation allowed)
__device__ float g_Q [PER];
__device__ float g_K [PER];
__device__ float g_V [PER];
__device__ float g_Q1[PER];
__device__ float g_Q2[PER];
__device__ float g_Q3[PER];
__device__ float g_Q4[PER];
__device__ float g_Q5[PER];
__device__ float g_Q6[PER];
__device__ float g_Hd[PER];

// ---------------------------------------------------------------------------
// Kernel A: projection GEMMs. 128x128 tile, 8x8 micro-tile, 256 threads.
// C[m][n] = sum_d X[m][d] * W[h][d][k], n=h*32+k. blockIdx.z = target 0..8.
// ---------------------------------------------------------------------------
__global__ __launch_bounds__(256, 2) void proj_gemm(
    const float* __restrict__ qsrc, const float* __restrict__ hsrc,
    const float* __restrict__ Wq,  const float* __restrict__ Wk,
    const float* __restrict__ Wv,  const float* __restrict__ W1,
    const float* __restrict__ W2,  const float* __restrict__ W3,
    const float* __restrict__ W4,  const float* __restrict__ W5,
    const float* __restrict__ W6)
{
    const int t = blockIdx.z;
    const float* src = (t == 0) ? qsrc : hsrc;
    const float* W;
    float* outp;
    switch (t) {
        case 0: W = Wq; outp = g_Q;  break;
        case 1: W = Wk; outp = g_K;  break;
        case 2: W = Wv; outp = g_V;  break;
        case 3: W = W1; outp = g_Q1; break;
        case 4: W = W2; outp = g_Q2; break;
        case 5: W = W3; outp = g_Q3; break;
        case 6: W = W4; outp = g_Q4; break;
        case 7: W = W5; outp = g_Q5; break;
        default: W = W6; outp = g_Q6; break;
    }

    __shared__ float Ash[16][132];
    __shared__ float Bsh[16][132];

    const int tid = threadIdx.x;
    const int m0 = blockIdx.x * 128;
    const int n0 = blockIdx.y * 128;
    const int cx = tid & 15;     // 16 col-groups (8 cols each, split halves)
    const int ry = tid >> 4;     // 16 row-groups (8 rows each, split halves)

    float acc[8][8];
#pragma unroll
    for (int i = 0; i < 8; i++)
#pragma unroll
        for (int j = 0; j < 8; j++) acc[i][j] = 0.f;

    for (int d0 = 0; d0 < 256; d0 += 16) {
        // A tile: 128 rows x 16 d, transposed into Ash[d][row]
#pragma unroll
        for (int i = 0; i < 2; i++) {
            int fid = tid + i * 256;
            int row = fid >> 2;
            int dg  = (fid & 3) * 4;
            int m   = m0 + row;
            float4 v = make_float4(0.f, 0.f, 0.f, 0.f);
            if (m < MROWS)
                v = *(const float4*)(src + (size_t)m * 256 + d0 + dg);
            Ash[dg + 0][row] = v.x;
            Ash[dg + 1][row] = v.y;
            Ash[dg + 2][row] = v.z;
            Ash[dg + 3][row] = v.w;
        }
        // B tile: 16 d x 128 n (W is [h][d][k], n=h*32+k)
#pragma unroll
        for (int i = 0; i < 2; i++) {
            int fid = tid + i * 256;
            int d   = fid >> 5;
            int nn  = (fid & 31) * 4;
            int n   = n0 + nn;
            float4 v = *(const float4*)(W + (size_t)(n >> 5) * 8192 +
                                        (size_t)(d0 + d) * 32 + (n & 31));
            *(float4*)&Bsh[d][nn] = v;
        }
        __syncthreads();

#pragma unroll
        for (int d = 0; d < 16; d++) {
            float4 a0 = *(const float4*)&Ash[d][ry * 4];
            float4 a1 = *(const float4*)&Ash[d][64 + ry * 4];
            float4 b0 = *(const float4*)&Bsh[d][cx * 4];
            float4 b1 = *(const float4*)&Bsh[d][64 + cx * 4];
            float ar[8] = {a0.x, a0.y, a0.z, a0.w, a1.x, a1.y, a1.z, a1.w};
            float br[8] = {b0.x, b0.y, b0.z, b0.w, b1.x, b1.y, b1.z, b1.w};
#pragma unroll
            for (int i = 0; i < 8; i++)
#pragma unroll
                for (int j = 0; j < 8; j++)
                    acc[i][j] = fmaf(ar[i], br[j], acc[i][j]);
        }
        __syncthreads();
    }

#pragma unroll
    for (int i = 0; i < 8; i++) {
        int row = (i < 4) ? (ry * 4 + i) : (64 + ry * 4 + (i - 4));
        int m = m0 + row;
        if (m >= MROWS) continue;
        int bb = m / GG, node = m % GG;
#pragma unroll
        for (int j = 0; j < 8; j++) {
            int n = n0 + ((j < 4) ? (cx * 4 + j) : (64 + cx * 4 + (j - 4)));
            int hh = n >> 5, kk = n & 31;
            outp[(((size_t)hh * BB + bb) * GG + node) * DKC + kk] = acc[i][j];
        }
    }
}

// ---------------------------------------------------------------------------
// Kernel B: fused attention, chunked-GEMM, 512 threads (16 warps).
//   P2: logit GEMM (2q x 8m register tiles, float4 q loads)
//   P3: softmax (warp per query)
//   P4: AV GEMM (warp per 32-key slice) + 16-way reduce
// ---------------------------------------------------------------------------
__device__ __forceinline__ float warpMaxf(float v) {
#pragma unroll
    for (int o = 16; o; o >>= 1) v = fmaxf(v, __shfl_xor_sync(0xffffffffu, v, o));
    return v;
}
__device__ __forceinline__ float warpSumf(float v) {
#pragma unroll
    for (int o = 16; o; o >>= 1) v += __shfl_xor_sync(0xffffffffu, v, o);
    return v;
}

__global__ __launch_bounds__(512, 1) void attn_kernel()
{
    extern __shared__ float sm[];
    float* Kt  = sm + OFF_KT;
    float* Vt  = sm + OFF_VT;
    float* L0b = sm + OFF_L0;
    float* Lxb = sm + OFF_LX;

    const int b  = blockIdx.x;
    const int hh = blockIdx.y;
    const int tid = threadIdx.x, lane = tid & 31, wid = tid >> 5;
    const size_t base = (((size_t)hh * BB + b) * GG) * DKC;
    const float NINF = -CUDART_INF_F;

    // zero pad columns 513..515
    if (tid < 96) {
        int k = tid / 3, cc = 513 + (tid - k * 3);
        Kt[k * PADM + cc] = 0.f;
        Vt[k * PADM + cc] = 0.f;
    }
    // load K/V transposed: Kt[k][m], Vt[k][m]
    for (int i = tid; i < GG * DKC; i += 512) {
        int m = i >> 5, k = i & 31;
        Kt[k * PADM + m] = g_K[base + i];
        Vt[k * PADM + m] = g_V[base + i];
    }
    __syncthreads();

    for (int c = 0; c < 33; c++) {
        const int q0 = c * 16;

        // ---- Phase 1: stage query vectors for this chunk ----
        for (int i = tid; i < 2048; i += 512) {
            int type = i >> 9, qq = (i >> 5) & 15, k = i & 31;
            int n = q0 + qq;
            float v = 0.f;
            if (n < GG) {
                size_t off = base + (size_t)n * 32 + k;
                bool pick = (n >= 1 && n <= NPP);
                if (type == 0)          v = g_Q[off];
                else if (n >= 1) {
                    if (type == 1)      v = pick ? g_Q2[off] : g_Q6[off];
                    else if (type == 2) v = pick ? g_Q3[off] : g_Q5[off];
                    else                v = pick ? g_Q1[off] : g_Q4[off];
                }
            }
            sm[OFF_QB + i] = v;
        }
        __syncthreads();

        // ---- Phase 2: logit GEMM (thread: 2 queries x 8 keys) ----
        {
            const int qg  = tid >> 6;          // 0..7 -> queries qg*2, qg*2+1
            const int qi0 = qg * 2;
            const int mt  = tid & 63;
            const int mA  = mt * 4;            // keys 0..255
            const int mB  = 256 + mt * 4;      // keys 256..511
            float L0r[2][8], Lxr[2][8];
#pragma unroll
            for (int q = 0; q < 2; q++)
#pragma unroll
                for (int j = 0; j < 8; j++) { L0r[q][j] = 0.f; Lxr[q][j] = 0.f; }

#pragma unroll
            for (int k4 = 0; k4 < 8; k4++) {
                float qv[2][4], u1[2][4], u2[2][4];
#pragma unroll
                for (int q = 0; q < 2; q++) {
                    *(float4*)qv[q] = *(const float4*)&sm[OFF_QB + (qi0 + q) * 32 + k4 * 4];
                    *(float4*)u1[q] = *(const float4*)&sm[OFF_U1 + (qi0 + q) * 32 + k4 * 4];
                    *(float4*)u2[q] = *(const float4*)&sm[OFF_U2 + (qi0 + q) * 32 + k4 * 4];
                }
#pragma unroll
                for (int kk = 0; kk < 4; kk++) {
                    int k = k4 * 4 + kk;
                    float4 ka = *(const float4*)&Kt[k * PADM + mA];
                    float4 kb = *(const float4*)&Kt[k * PADM + mB];
#pragma unroll
                    for (int q = 0; q < 2; q++) {
                        float qs  = qv[q][kk];
                        float u1s = u1[q][kk];
                        float u2s = u2[q][kk];
                        L0r[q][0] = fmaf(qs, ka.x, L0r[q][0]);
                        L0r[q][1] = fmaf(qs, ka.y, L0r[q][1]);
                        L0r[q][2] = fmaf(qs, ka.z, L0r[q][2]);
                        L0r[q][3] = fmaf(qs, ka.w, L0r[q][3]);
                        L0r[q][4] = fmaf(qs, kb.x, L0r[q][4]);
                        L0r[q][5] = fmaf(qs, kb.y, L0r[q][5]);
                        L0r[q][6] = fmaf(qs, kb.z, L0r[q][6]);
                        L0r[q][7] = fmaf(qs, kb.w, L0r[q][7]);
                        Lxr[q][0] = fmaf(u1s, ka.x, Lxr[q][0]);
                        Lxr[q][1] = fmaf(u1s, ka.y, Lxr[q][1]);
                        Lxr[q][2] = fmaf(u1s, ka.z, Lxr[q][2]);
                        Lxr[q][3] = fmaf(u1s, ka.w, Lxr[q][3]);
                        Lxr[q][4] = fmaf(u2s, kb.x, Lxr[q][4]);
                        Lxr[q][5] = fmaf(u2s, kb.y, Lxr[q][5]);
                        Lxr[q][6] = fmaf(u2s, kb.z, Lxr[q][6]);
                        Lxr[q][7] = fmaf(u2s, kb.w, Lxr[q][7]);
                        if (mt == 0)   // m==256 is a pick key: uses u1, not u2
                            Lxr[q][4] = fmaf(u1s - u2s, kb.x, Lxr[q][4]);
                    }
                }
            }
#pragma unroll
            for (int q = 0; q < 2; q++) {
                int qrow = qi0 + q;
                if (mt == 0) Lxr[q][0] = NINF;   // m==0: no extra logit
                float4 oa = make_float4(L0r[q][0]*NORMC, L0r[q][1]*NORMC,
                                        L0r[q][2]*NORMC, L0r[q][3]*NORMC);
                float4 ob = make_float4(L0r[q][4]*NORMC, L0r[q][5]*NORMC,
                                        L0r[q][6]*NORMC, L0r[q][7]*NORMC);
                *(float4*)&L0b[qrow * LPAD + mA] = oa;
                *(float4*)&L0b[qrow * LPAD + mB] = ob;
                float4 xa = make_float4(Lxr[q][0]*NORMC, Lxr[q][1]*NORMC,
                                        Lxr[q][2]*NORMC, Lxr[q][3]*NORMC);
                float4 xb = make_float4(Lxr[q][4]*NORMC, Lxr[q][5]*NORMC,
                                        Lxr[q][6]*NORMC, Lxr[q][7]*NORMC);
                *(float4*)&Lxb[qrow * LPAD + mA] = xa;
                *(float4*)&Lxb[qrow * LPAD + mB] = xb;
            }
        }
        __syncthreads();

        // ---- Phase 3: softmax (warp per query) ----
        {
            int qq = wid;
            int n = q0 + qq;
            float* wrow = &L0b[qq * LPAD];
            float* xrow = &Lxb[qq * LPAD];
            if (n < GG) {
                const bool useX = (n >= 1);
                float kv512 = Kt[lane * PADM + 512];
                float l0_512 = NORMC * warpSumf(sm[OFF_QB + qq*32 + lane] * kv512);
                float lx512 = NINF, lp = NINF;
                int p = 0;
                if (useX) {
                    lx512 = NORMC * warpSumf(sm[OFF_U2 + qq*32 + lane] * kv512);
                    p = (n <= NPP) ? n + NPP : n - NPP;
                    float kvp = Kt[lane * PADM + p];
                    lp = NORMC * warpSumf(sm[OFF_QA + qq*32 + lane] * kvp);
                }
                float mx = fmaxf(l0_512, fmaxf(lx512, lp));
#pragma unroll
                for (int i = 0; i < 4; i++) {
                    int m4 = i * 128 + lane * 4;
                    float4 a = *(const float4*)&wrow[m4];
                    mx = fmaxf(mx, fmaxf(fmaxf(a.x, a.y), fmaxf(a.z, a.w)));
                    if (useX) {
                        float4 x = *(const float4*)&xrow[m4];
                        mx = fmaxf(mx, fmaxf(fmaxf(x.x, x.y), fmaxf(x.z, x.w)));
                    }
                }
                mx = warpMaxf(mx);
                float tot = 0.f;
#pragma unroll
                for (int i = 0; i < 4; i++) {
                    int m4 = i * 128 + lane * 4;
                    float4 a = *(const float4*)&wrow[m4];
                    float4 wv;
                    wv.x = __expf(a.x - mx); wv.y = __expf(a.y - mx);
                    wv.z = __expf(a.z - mx); wv.w = __expf(a.w - mx);
                    if (useX) {
                        float4 x = *(const float4*)&xrow[m4];
                        wv.x += __expf(x.x - mx); wv.y += __expf(x.y - mx);
                        wv.z += __expf(x.z - mx); wv.w += __expf(x.w - mx);
                    }
                    tot += wv.x + wv.y + wv.z + wv.w;
                    *(float4*)&wrow[m4] = wv;
                }
                tot = warpSumf(tot);
                float w512 = __expf(l0_512 - mx) + (useX ? __expf(lx512 - mx) : 0.f);
                float wp   = useX ? __expf(lp - mx) : 0.f;
                tot += w512 + wp;
                __syncwarp();
                if (lane == 0) {
                    wrow[512] = w512;
                    if (useX) wrow[p] += wp;
                    wrow[513] = 0.f; wrow[514] = 0.f; wrow[515] = 0.f;
                    sm[OFF_TOT + qq] = 1.0f / tot;
                }
            } else {
                for (int i = lane; i < 129; i += 32)
                    *(float4*)&wrow[i * 4] = make_float4(0.f, 0.f, 0.f, 0.f);
                if (lane == 0) sm[OFF_TOT + qq] = 0.f;
            }
        }
        __syncthreads();

        // ---- Phase 4: AV GEMM (warp per 32-key slice) ----
        {
            float acc[16];
#pragma unroll
            for (int qq = 0; qq < 16; qq++) acc[qq] = 0.f;
            const int iters = (wid == 15) ? 9 : 8;
            const int mbase = wid * 32;
            for (int it = 0; it < iters; it++) {
                int m4 = mbase + it * 4;
                float4 v = *(const float4*)&Vt[lane * PADM + m4];
#pragma unroll
                for (int qq = 0; qq < 16; qq++) {
                    float4 wv = *(const float4*)&L0b[qq * LPAD + m4];
                    acc[qq] = fmaf(wv.x, v.x, acc[qq]);
                    acc[qq] = fmaf(wv.y, v.y, acc[qq]);
                    acc[qq] = fmaf(wv.z, v.z, acc[qq]);
                    acc[qq] = fmaf(wv.w, v.w, acc[qq]);
                }
            }
#pragma unroll
            for (int qq = 0; qq < 16; qq++)
                Lxb[(wid * 16 + qq) * 32 + lane] = acc[qq];
        }
        __syncthreads();

        // ---- Phase 5: 16-way reduce + writeout (thread per output) ----
        {
            int qq = tid >> 5, k = tid & 31;
            float s = 0.f;
#pragma unroll
            for (int w = 0; w < 16; w++)
                s += Lxb[(w * 16 + qq) * 32 + k];
            int n = q0 + qq;
            if (n < GG)
                g_Hd[base + (size_t)n * 32 + k] = s * sm[OFF_TOT + qq];
        }
        __syncthreads();
    }
}

// ---------------------------------------------------------------------------
// Kernel C: output projection (unchanged)
// ---------------------------------------------------------------------------
__global__ __launch_bounds__(256) void out_gemm(
    const float* __restrict__ Wout, float* __restrict__ out)
{
    __shared__ float Ash[16][132];
    __shared__ float Bsh[16][68];

    const int tid = threadIdx.x;
    const int m0 = blockIdx.x * 128;
    const int n0 = blockIdx.y * 64;
    const int cx = tid & 15;
    const int ry = tid >> 4;

    float acc[8][4];
#pragma unroll
    for (int i = 0; i < 8; i++)
#pragma unroll
        for (int j = 0; j < 4; j++) acc[i][j] = 0.f;

    for (int d0 = 0; d0 < 256; d0 += 16) {
#pragma unroll
        for (int i = 0; i < 2; i++) {
            int fid = tid + i * 256;
            int row = fid >> 2;
            int cg  = (fid & 3) * 4;
            int m   = m0 + row;
            int cc  = d0 + cg;
            float4 v = make_float4(0.f, 0.f, 0.f, 0.f);
            if (m < MROWS)
                v = *(const float4*)(g_Hd + (size_t)(cc >> 5) * MROWS * DKC +
                                     (size_t)m * DKC + (cc & 31));
            Ash[cg + 0][row] = v.x;
            Ash[cg + 1][row] = v.y;
            Ash[cg + 2][row] = v.z;
            Ash[cg + 3][row] = v.w;
        }
        {
            int d  = tid >> 4;
            int nn = (tid & 15) * 4;
            float4 v = *(const float4*)(Wout + (size_t)(d0 + d) * EE + n0 + nn);
            *(float4*)&Bsh[d][nn] = v;
        }
        __syncthreads();

#pragma unroll
        for (int d = 0; d < 16; d++) {
            float4 a0 = *(const float4*)&Ash[d][ry * 4];
            float4 a1 = *(const float4*)&Ash[d][64 + ry * 4];
            float4 bv = *(const float4*)&Bsh[d][cx * 4];
            float ar[8] = {a0.x, a0.y, a0.z, a0.w, a1.x, a1.y, a1.z, a1.w};
            float br[4] = {bv.x, bv.y, bv.z, bv.w};
#pragma unroll
            for (int i = 0; i < 8; i++)
#pragma unroll
                for (int j = 0; j < 4; j++)
                    acc[i][j] = fmaf(ar[i], br[j], acc[i][j]);
        }
        __syncthreads();
    }

#pragma unroll
    for (int i = 0; i < 8; i++) {
        int row = (i < 4) ? (ry * 4 + i) : (64 + ry * 4 + (i - 4));
        int m = m0 + row;
        if (m >= MROWS) continue;
#pragma unroll
        for (int j = 0; j < 4; j++) {
            out[(size_t)m * EE + n0 + cx * 4 + j] = acc[i][j];
        }
    }
}

// ---------------------------------------------------------------------------
extern "C" void kernel_launch(void* const* d_in, const int* in_sizes, int n_in,
                              void* d_out, int out_size)
{
    (void)in_sizes; (void)n_in; (void)out_size;
    const float* q    = (const float*)d_in[0];
    const float* h    = (const float*)d_in[1];
    const float* Wq   = (const float*)d_in[2];
    const float* Wk   = (const float*)d_in[3];
    const float* Wv   = (const float*)d_in[4];
    const float* W1   = (const float*)d_in[5];
    const float* W2   = (const float*)d_in[6];
    const float* W3   = (const float*)d_in[7];
    const float* W4   = (const float*)d_in[8];
    const float* W5   = (const float*)d_in[9];
    const float* W6   = (const float*)d_in[10];
    const float* Wout = (const float*)d_in[11];
    float* out = (float*)d_out;

    const int SMEM_ATTN = SMEM_FLOATS * (int)sizeof(float);  // 206912 B
    cudaFuncSetAttribute(attn_kernel,
                         cudaFuncAttributeMaxDynamicSharedMemorySize, SMEM_ATTN);

    dim3 gridP((MROWS + 127) / 128, 2, 9);     // 65 x 2 x 9 (128x128 tiles)
    proj_gemm<<<gridP, 256>>>(q, h, Wq, Wk, Wv, W1, W2, W3, W4, W5, W6);

    dim3 gridA(BB, HH);                        // 16 x 8
    attn_kernel<<<gridA, 512, SMEM_ATTN>>>();

    dim3 gridO((MROWS + 127) / 128, 4);        // 65 x 4
    out_gemm<<<gridO, 256>>>(Wout, out);
}

// round 10
// speedup vs baseline: 1.5569x; 1.1331x over previous
#include <cuda_runtime.h>
#include <math_constants.h>

// Problem constants
#define HH   8
#define BB   16
#define GG   513
#define DD   256
#define DKC  32
#define EE   256
#define NPP  256
#define MROWS (BB*GG)            // 8208
#define MHALF (BB*NPP)           // 4096
#define PER  (HH*BB*GG*DKC)      // 2101248
#define NORMC 0.17677669529663687f

// attn smem layout (float offsets)
#define PADM 516                 // Kt/Vt row pad (516 % 32 == 4 -> conflict-free f4)
#define LPAD 520                 // logit/weight row pad
#define OFF_KT  0                // Kt[32][516]
#define OFF_VT  16512            // Vt[32][516]
#define OFF_L0  33024            // L0b[16][520]
#define OFF_LX  41344            // Lxb[16][520]
#define OFF_QB  49664            // qb [16][32]
#define OFF_U1  50176
#define OFF_U2  50688
#define OFF_QA  51200
#define OFF_TOT 51712            // invtot[16]
#define SMEM_FLOATS 51728        // 206912 bytes

// Scratch (device globals; no allocation allowed)
__device__ float g_Q [PER];
__device__ float g_K [PER];
__device__ float g_V [PER];
__device__ float g_Q1[PER];
__device__ float g_Q2[PER];
__device__ float g_Q3[PER];
__device__ float g_Q4[PER];
__device__ float g_Q5[PER];
__device__ float g_Q6[PER];
__device__ float g_Hd[PER];

// ---------------------------------------------------------------------------
// Kernel A: projection GEMMs. 128x128 tile, 8x8 micro-tile, 256 threads.
// Targets 0..2 (Q,K,V): all 8208 rows. Targets 3..5 (W1..W3): pick rows only
// (4096 compressed). Targets 6..8 (W4..W6): delivery rows only.
// ---------------------------------------------------------------------------
__global__ __launch_bounds__(256, 2) void proj_gemm(
    const float* __restrict__ qsrc, const float* __restrict__ hsrc,
    const float* __restrict__ Wq,  const float* __restrict__ Wk,
    const float* __restrict__ Wv,  const float* __restrict__ W1,
    const float* __restrict__ W2,  const float* __restrict__ W3,
    const float* __restrict__ W4,  const float* __restrict__ W5,
    const float* __restrict__ W6)
{
    const int t = blockIdx.z;
    const bool half = (t >= 3);
    if (half && blockIdx.x >= MHALF / 128) return;   // 32 tiles cover 4096 rows
    const int nodeoff = (t >= 6) ? (1 + NPP) : 1;    // pick: 1..256, delivery: 257..512
    const int Mtot = half ? MHALF : MROWS;

    const float* src = (t == 0) ? qsrc : hsrc;
    const float* W;
    float* outp;
    switch (t) {
        case 0: W = Wq; outp = g_Q;  break;
        case 1: W = Wk; outp = g_K;  break;
        case 2: W = Wv; outp = g_V;  break;
        case 3: W = W1; outp = g_Q1; break;
        case 4: W = W2; outp = g_Q2; break;
        case 5: W = W3; outp = g_Q3; break;
        case 6: W = W4; outp = g_Q4; break;
        case 7: W = W5; outp = g_Q5; break;
        default: W = W6; outp = g_Q6; break;
    }

    __shared__ float Ash[16][132];
    __shared__ float Bsh[16][132];

    const int tid = threadIdx.x;
    const int m0 = blockIdx.x * 128;
    const int n0 = blockIdx.y * 128;
    const int cx = tid & 15;
    const int ry = tid >> 4;

    float acc[8][8];
#pragma unroll
    for (int i = 0; i < 8; i++)
#pragma unroll
        for (int j = 0; j < 8; j++) acc[i][j] = 0.f;

    for (int d0 = 0; d0 < 256; d0 += 16) {
        // A tile: 128 rows x 16 d, transposed into Ash[d][row]
#pragma unroll
        for (int i = 0; i < 2; i++) {
            int fid = tid + i * 256;
            int row = fid >> 2;
            int dg  = (fid & 3) * 4;
            int m   = m0 + row;
            float4 v = make_float4(0.f, 0.f, 0.f, 0.f);
            if (m < Mtot) {
                size_t srow = half
                    ? ((size_t)(m >> 8) * GG + nodeoff + (m & 255))
                    : (size_t)m;
                v = *(const float4*)(src + srow * 256 + d0 + dg);
            }
            Ash[dg + 0][row] = v.x;
            Ash[dg + 1][row] = v.y;
            Ash[dg + 2][row] = v.z;
            Ash[dg + 3][row] = v.w;
        }
        // B tile: 16 d x 128 n (W is [h][d][k], n=h*32+k)
#pragma unroll
        for (int i = 0; i < 2; i++) {
            int fid = tid + i * 256;
            int d   = fid >> 5;
            int nn  = (fid & 31) * 4;
            int n   = n0 + nn;
            float4 v = *(const float4*)(W + (size_t)(n >> 5) * 8192 +
                                        (size_t)(d0 + d) * 32 + (n & 31));
            *(float4*)&Bsh[d][nn] = v;
        }
        __syncthreads();

#pragma unroll
        for (int d = 0; d < 16; d++) {
            float4 a0 = *(const float4*)&Ash[d][ry * 4];
            float4 a1 = *(const float4*)&Ash[d][64 + ry * 4];
            float4 b0 = *(const float4*)&Bsh[d][cx * 4];
            float4 b1 = *(const float4*)&Bsh[d][64 + cx * 4];
            float ar[8] = {a0.x, a0.y, a0.z, a0.w, a1.x, a1.y, a1.z, a1.w};
            float br[8] = {b0.x, b0.y, b0.z, b0.w, b1.x, b1.y, b1.z, b1.w};
#pragma unroll
            for (int i = 0; i < 8; i++)
#pragma unroll
                for (int j = 0; j < 8; j++)
                    acc[i][j] = fmaf(ar[i], br[j], acc[i][j]);
        }
        __syncthreads();
    }

#pragma unroll
    for (int i = 0; i < 8; i++) {
        int row = (i < 4) ? (ry * 4 + i) : (64 + ry * 4 + (i - 4));
        int m = m0 + row;
        if (m >= Mtot) continue;
        int bb, node;
        if (half) { bb = m >> 8; node = nodeoff + (m & 255); }
        else      { bb = m / GG; node = m % GG; }
#pragma unroll
        for (int j = 0; j < 8; j++) {
            int n = n0 + ((j < 4) ? (cx * 4 + j) : (64 + cx * 4 + (j - 4)));
            int hh = n >> 5, kk = n & 31;
            outp[(((size_t)hh * BB + bb) * GG + node) * DKC + kk] = acc[i][j];
        }
    }
}

// ---------------------------------------------------------------------------
// Kernel B: fused attention, chunked-GEMM, 512 threads (16 warps).
//   P2: logit GEMM (2q x 8m register tiles); key-256 correction deferred to P3
//   P3: softmax (warp per query); fixes xrow[256] via warp reduction
//   P4: AV GEMM (warp per 32-key slice) + 16-way reduce
// ---------------------------------------------------------------------------
__device__ __forceinline__ float warpMaxf(float v) {
#pragma unroll
    for (int o = 16; o; o >>= 1) v = fmaxf(v, __shfl_xor_sync(0xffffffffu, v, o));
    return v;
}
__device__ __forceinline__ float warpSumf(float v) {
#pragma unroll
    for (int o = 16; o; o >>= 1) v += __shfl_xor_sync(0xffffffffu, v, o);
    return v;
}

__global__ __launch_bounds__(512, 1) void attn_kernel()
{
    extern __shared__ float sm[];
    float* Kt  = sm + OFF_KT;
    float* Vt  = sm + OFF_VT;
    float* L0b = sm + OFF_L0;
    float* Lxb = sm + OFF_LX;

    const int b  = blockIdx.x;
    const int hh = blockIdx.y;
    const int tid = threadIdx.x, lane = tid & 31, wid = tid >> 5;
    const size_t base = (((size_t)hh * BB + b) * GG) * DKC;
    const float NINF = -CUDART_INF_F;

    // zero pad columns 513..515
    if (tid < 96) {
        int k = tid / 3, cc = 513 + (tid - k * 3);
        Kt[k * PADM + cc] = 0.f;
        Vt[k * PADM + cc] = 0.f;
    }
    // load K/V transposed: Kt[k][m], Vt[k][m]
    for (int i = tid; i < GG * DKC; i += 512) {
        int m = i >> 5, k = i & 31;
        Kt[k * PADM + m] = g_K[base + i];
        Vt[k * PADM + m] = g_V[base + i];
    }
    __syncthreads();

    for (int c = 0; c < 33; c++) {
        const int q0 = c * 16;

        // ---- Phase 1: stage query vectors for this chunk ----
        for (int i = tid; i < 2048; i += 512) {
            int type = i >> 9, qq = (i >> 5) & 15, k = i & 31;
            int n = q0 + qq;
            float v = 0.f;
            if (n < GG) {
                size_t off = base + (size_t)n * 32 + k;
                bool pick = (n >= 1 && n <= NPP);
                if (type == 0)          v = g_Q[off];
                else if (n >= 1) {
                    if (type == 1)      v = pick ? g_Q2[off] : g_Q6[off];
                    else if (type == 2) v = pick ? g_Q3[off] : g_Q5[off];
                    else                v = pick ? g_Q1[off] : g_Q4[off];
                }
            }
            sm[OFF_QB + i] = v;
        }
        __syncthreads();

        // ---- Phase 2: logit GEMM (thread: 2 queries x 8 keys) ----
        {
            const int qg  = tid >> 6;          // 0..7 -> queries qg*2, qg*2+1
            const int qi0 = qg * 2;
            const int mt  = tid & 63;
            const int mA  = mt * 4;            // keys 0..255
            const int mB  = 256 + mt * 4;      // keys 256..511
            float L0r[2][8], Lxr[2][8];
#pragma unroll
            for (int q = 0; q < 2; q++)
#pragma unroll
                for (int j = 0; j < 8; j++) { L0r[q][j] = 0.f; Lxr[q][j] = 0.f; }

#pragma unroll
            for (int k4 = 0; k4 < 8; k4++) {
                float qv[2][4], u1[2][4], u2[2][4];
#pragma unroll
                for (int q = 0; q < 2; q++) {
                    *(float4*)qv[q] = *(const float4*)&sm[OFF_QB + (qi0 + q) * 32 + k4 * 4];
                    *(float4*)u1[q] = *(const float4*)&sm[OFF_U1 + (qi0 + q) * 32 + k4 * 4];
                    *(float4*)u2[q] = *(const float4*)&sm[OFF_U2 + (qi0 + q) * 32 + k4 * 4];
                }
#pragma unroll
                for (int kk = 0; kk < 4; kk++) {
                    int k = k4 * 4 + kk;
                    float4 ka = *(const float4*)&Kt[k * PADM + mA];
                    float4 kb = *(const float4*)&Kt[k * PADM + mB];
#pragma unroll
                    for (int q = 0; q < 2; q++) {
                        float qs  = qv[q][kk];
                        float u1s = u1[q][kk];
                        float u2s = u2[q][kk];
                        L0r[q][0] = fmaf(qs, ka.x, L0r[q][0]);
                        L0r[q][1] = fmaf(qs, ka.y, L0r[q][1]);
                        L0r[q][2] = fmaf(qs, ka.z, L0r[q][2]);
                        L0r[q][3] = fmaf(qs, ka.w, L0r[q][3]);
                        L0r[q][4] = fmaf(qs, kb.x, L0r[q][4]);
                        L0r[q][5] = fmaf(qs, kb.y, L0r[q][5]);
                        L0r[q][6] = fmaf(qs, kb.z, L0r[q][6]);
                        L0r[q][7] = fmaf(qs, kb.w, L0r[q][7]);
                        Lxr[q][0] = fmaf(u1s, ka.x, Lxr[q][0]);
                        Lxr[q][1] = fmaf(u1s, ka.y, Lxr[q][1]);
                        Lxr[q][2] = fmaf(u1s, ka.z, Lxr[q][2]);
                        Lxr[q][3] = fmaf(u1s, ka.w, Lxr[q][3]);
                        Lxr[q][4] = fmaf(u2s, kb.x, Lxr[q][4]);
                        Lxr[q][5] = fmaf(u2s, kb.y, Lxr[q][5]);
                        Lxr[q][6] = fmaf(u2s, kb.z, Lxr[q][6]);
                        Lxr[q][7] = fmaf(u2s, kb.w, Lxr[q][7]);
                    }
                }
            }
#pragma unroll
            for (int q = 0; q < 2; q++) {
                int qrow = qi0 + q;
                if (mt == 0) Lxr[q][0] = NINF;   // m==0: no extra logit
                float4 oa = make_float4(L0r[q][0]*NORMC, L0r[q][1]*NORMC,
                                        L0r[q][2]*NORMC, L0r[q][3]*NORMC);
                float4 ob = make_float4(L0r[q][4]*NORMC, L0r[q][5]*NORMC,
                                        L0r[q][6]*NORMC, L0r[q][7]*NORMC);
                *(float4*)&L0b[qrow * LPAD + mA] = oa;
                *(float4*)&L0b[qrow * LPAD + mB] = ob;
                float4 xa = make_float4(Lxr[q][0]*NORMC, Lxr[q][1]*NORMC,
                                        Lxr[q][2]*NORMC, Lxr[q][3]*NORMC);
                float4 xb = make_float4(Lxr[q][4]*NORMC, Lxr[q][5]*NORMC,
                                        Lxr[q][6]*NORMC, Lxr[q][7]*NORMC);
                *(float4*)&Lxb[qrow * LPAD + mA] = xa;
                *(float4*)&Lxb[qrow * LPAD + mB] = xb;
            }
        }
        __syncthreads();

        // ---- Phase 3: softmax (warp per query) ----
        {
            int qq = wid;
            int n = q0 + qq;
            float* wrow = &L0b[qq * LPAD];
            float* xrow = &Lxb[qq * LPAD];
            if (n < GG) {
                const bool useX = (n >= 1);
                float kv512 = Kt[lane * PADM + 512];
                float l0_512 = NORMC * warpSumf(sm[OFF_QB + qq*32 + lane] * kv512);
                float lx512 = NINF, lp = NINF;
                int p = 0;
                if (useX) {
                    lx512 = NORMC * warpSumf(sm[OFF_U2 + qq*32 + lane] * kv512);
                    p = (n <= NPP) ? n + NPP : n - NPP;
                    float kvp = Kt[lane * PADM + p];
                    lp = NORMC * warpSumf(sm[OFF_QA + qq*32 + lane] * kvp);
                    // key 256 is a PICK key: its extra logit uses u1, not u2.
                    // P2 computed it with u2; recompute correctly here.
                    float kv256 = Kt[lane * PADM + 256];
                    float lx256 = NORMC * warpSumf(sm[OFF_U1 + qq*32 + lane] * kv256);
                    if (lane == 0) xrow[256] = lx256;
                    __syncwarp();
                }
                float mx = fmaxf(l0_512, fmaxf(lx512, lp));
#pragma unroll
                for (int i = 0; i < 4; i++) {
                    int m4 = i * 128 + lane * 4;
                    float4 a = *(const float4*)&wrow[m4];
                    mx = fmaxf(mx, fmaxf(fmaxf(a.x, a.y), fmaxf(a.z, a.w)));
                    if (useX) {
                        float4 x = *(const float4*)&xrow[m4];
                        mx = fmaxf(mx, fmaxf(fmaxf(x.x, x.y), fmaxf(x.z, x.w)));
                    }
                }
                mx = warpMaxf(mx);
                float tot = 0.f;
#pragma unroll
                for (int i = 0; i < 4; i++) {
                    int m4 = i * 128 + lane * 4;
                    float4 a = *(const float4*)&wrow[m4];
                    float4 wv;
                    wv.x = __expf(a.x - mx); wv.y = __expf(a.y - mx);
                    wv.z = __expf(a.z - mx); wv.w = __expf(a.w - mx);
                    if (useX) {
                        float4 x = *(const float4*)&xrow[m4];
                        wv.x += __expf(x.x - mx); wv.y += __expf(x.y - mx);
                        wv.z += __expf(x.z - mx); wv.w += __expf(x.w - mx);
                    }
                    tot += wv.x + wv.y + wv.z + wv.w;
                    *(float4*)&wrow[m4] = wv;
                }
                tot = warpSumf(tot);
                float w512 = __expf(l0_512 - mx) + (useX ? __expf(lx512 - mx) : 0.f);
                float wp   = useX ? __expf(lp - mx) : 0.f;
                tot += w512 + wp;
                __syncwarp();
                if (lane == 0) {
                    wrow[512] = w512;
                    if (useX) wrow[p] += wp;
                    wrow[513] = 0.f; wrow[514] = 0.f; wrow[515] = 0.f;
                    sm[OFF_TOT + qq] = 1.0f / tot;
                }
            } else {
                for (int i = lane; i < 129; i += 32)
                    *(float4*)&wrow[i * 4] = make_float4(0.f, 0.f, 0.f, 0.f);
                if (lane == 0) sm[OFF_TOT + qq] = 0.f;
            }
        }
        __syncthreads();

        // ---- Phase 4: AV GEMM (warp per 32-key slice) ----
        {
            float acc[16];
#pragma unroll
            for (int qq = 0; qq < 16; qq++) acc[qq] = 0.f;
            const int iters = (wid == 15) ? 9 : 8;
            const int mbase = wid * 32;
            for (int it = 0; it < iters; it++) {
                int m4 = mbase + it * 4;
                float4 v = *(const float4*)&Vt[lane * PADM + m4];
#pragma unroll
                for (int qq = 0; qq < 16; qq++) {
                    float4 wv = *(const float4*)&L0b[qq * LPAD + m4];
                    acc[qq] = fmaf(wv.x, v.x, acc[qq]);
                    acc[qq] = fmaf(wv.y, v.y, acc[qq]);
                    acc[qq] = fmaf(wv.z, v.z, acc[qq]);
                    acc[qq] = fmaf(wv.w, v.w, acc[qq]);
                }
            }
#pragma unroll
            for (int qq = 0; qq < 16; qq++)
                Lxb[(wid * 16 + qq) * 32 + lane] = acc[qq];
        }
        __syncthreads();

        // ---- Phase 5: 16-way reduce + writeout (thread per output) ----
        {
            int qq = tid >> 5, k = tid & 31;
            float s = 0.f;
#pragma unroll
            for (int w = 0; w < 16; w++)
                s += Lxb[(w * 16 + qq) * 32 + k];
            int n = q0 + qq;
            if (n < GG)
                g_Hd[base + (size_t)n * 32 + k] = s * sm[OFF_TOT + qq];
        }
        __syncthreads();
    }
}

// ---------------------------------------------------------------------------
// Kernel C: output projection (unchanged)
// ---------------------------------------------------------------------------
__global__ __launch_bounds__(256) void out_gemm(
    const float* __restrict__ Wout, float* __restrict__ out)
{
    __shared__ float Ash[16][132];
    __shared__ float Bsh[16][68];

    const int tid = threadIdx.x;
    const int m0 = blockIdx.x * 128;
    const int n0 = blockIdx.y * 64;
    const int cx = tid & 15;
    const int ry = tid >> 4;

    float acc[8][4];
#pragma unroll
    for (int i = 0; i < 8; i++)
#pragma unroll
        for (int j = 0; j < 4; j++) acc[i][j] = 0.f;

    for (int d0 = 0; d0 < 256; d0 += 16) {
#pragma unroll
        for (int i = 0; i < 2; i++) {
            int fid = tid + i * 256;
            int row = fid >> 2;
            int cg  = (fid & 3) * 4;
            int m   = m0 + row;
            int cc  = d0 + cg;
            float4 v = make_float4(0.f, 0.f, 0.f, 0.f);
            if (m < MROWS)
                v = *(const float4*)(g_Hd + (size_t)(cc >> 5) * MROWS * DKC +
                                     (size_t)m * DKC + (cc & 31));
            Ash[cg + 0][row] = v.x;
            Ash[cg + 1][row] = v.y;
            Ash[cg + 2][row] = v.z;
            Ash[cg + 3][row] = v.w;
        }
        {
            int d  = tid >> 4;
            int nn = (tid & 15) * 4;
            float4 v = *(const float4*)(Wout + (size_t)(d0 + d) * EE + n0 + nn);
            *(float4*)&Bsh[d][nn] = v;
        }
        __syncthreads();

#pragma unroll
        for (int d = 0; d < 16; d++) {
            float4 a0 = *(const float4*)&Ash[d][ry * 4];
            float4 a1 = *(const float4*)&Ash[d][64 + ry * 4];
            float4 bv = *(const float4*)&Bsh[d][cx * 4];
            float ar[8] = {a0.x, a0.y, a0.z, a0.w, a1.x, a1.y, a1.z, a1.w};
            float br[4] = {bv.x, bv.y, bv.z, bv.w};
#pragma unroll
            for (int i = 0; i < 8; i++)
#pragma unroll
                for (int j = 0; j < 4; j++)
                    acc[i][j] = fmaf(ar[i], br[j], acc[i][j]);
        }
        __syncthreads();
    }

#pragma unroll
    for (int i = 0; i < 8; i++) {
        int row = (i < 4) ? (ry * 4 + i) : (64 + ry * 4 + (i - 4));
        int m = m0 + row;
        if (m >= MROWS) continue;
#pragma unroll
        for (int j = 0; j < 4; j++) {
            out[(size_t)m * EE + n0 + cx * 4 + j] = acc[i][j];
        }
    }
}

// ---------------------------------------------------------------------------
extern "C" void kernel_launch(void* const* d_in, const int* in_sizes, int n_in,
                              void* d_out, int out_size)
{
    (void)in_sizes; (void)n_in; (void)out_size;
    const float* q    = (const float*)d_in[0];
    const float* h    = (const float*)d_in[1];
    const float* Wq   = (const float*)d_in[2];
    const float* Wk   = (const float*)d_in[3];
    const float* Wv   = (const float*)d_in[4];
    const float* W1   = (const float*)d_in[5];
    const float* W2   = (const float*)d_in[6];
    const float* W3   = (const float*)d_in[7];
    const float* W4   = (const float*)d_in[8];
    const float* W5   = (const float*)d_in[9];
    const float* W6   = (const float*)d_in[10];
    const float* Wout = (const float*)d_in[11];
    float* out = (float*)d_out;

    const int SMEM_ATTN = SMEM_FLOATS * (int)sizeof(float);  // 206912 B
    cudaFuncSetAttribute(attn_kernel,
                         cudaFuncAttributeMaxDynamicSharedMemorySize, SMEM_ATTN);

    dim3 gridP((MROWS + 127) / 128, 2, 9);     // 65 x 2 x 9; half targets exit early past x=31
    proj_gemm<<<gridP, 256>>>(q, h, Wq, Wk, Wv, W1, W2, W3, W4, W5, W6);

    dim3 gridA(BB, HH);                        // 16 x 8
    attn_kernel<<<gridA, 512, SMEM_ATTN>>>();

    dim3 gridO((MROWS + 127) / 128, 4);        // 65 x 4
    out_gemm<<<gridO, 256>>>(Wout, out);
}

// round 12
// speedup vs baseline: 1.6394x; 1.0531x over previous
#include <cuda_runtime.h>
#include <math_constants.h>

// Problem constants
#define HH   8
#define BB   16
#define GG   513
#define DD   256
#define DKC  32
#define EE   256
#define NPP  256
#define MROWS (BB*GG)            // 8208
#define MHALF (BB*NPP)           // 4096
#define PER  (HH*BB*GG*DKC)      // 2101248
#define NORMC 0.17677669529663687f

// attn smem layout (float offsets)
#define PADM 516
#define LPAD 520
#define OFF_KT  0
#define OFF_VT  16512
#define OFF_L0  33024
#define OFF_LX  41344
#define OFF_QB  49664
#define OFF_U1  50176
#define OFF_U2  50688
#define OFF_QA  51200
#define OFF_TOT 51712
#define SMEM_FLOATS 51728        // 206912 bytes

typedef unsigned long long u64;

// packed f32x2 helpers (Blackwell FFMA2 path)
__device__ __forceinline__ u64 pk2(float lo, float hi) {
    u64 r; asm("mov.b64 %0, {%1, %2};" : "=l"(r) : "f"(lo), "f"(hi)); return r;
}
__device__ __forceinline__ float2 upk2(u64 v) {
    float2 f; asm("mov.b64 {%0, %1}, %2;" : "=f"(f.x), "=f"(f.y) : "l"(v)); return f;
}
#define FMA2(d, a, b) asm("fma.rn.f32x2 %0, %1, %2, %0;" : "+l"(d) : "l"(a), "l"(b))

// Scratch (device globals; no allocation allowed)
__device__ float g_Q [PER];
__device__ float g_K [PER];
__device__ float g_V [PER];
__device__ float g_Q1[PER];
__device__ float g_Q2[PER];
__device__ float g_Q3[PER];
__device__ float g_Q4[PER];
__device__ float g_Q5[PER];
__device__ float g_Q6[PER];
__device__ float g_Hd[PER];

// ---------------------------------------------------------------------------
// Kernel A: projection GEMMs. 128x128 tile, 8x8 micro-tile (f32x2 packed).
// Targets 0..2: all rows; 3..5: pick rows only; 6..8: delivery rows only.
// ---------------------------------------------------------------------------
__global__ __launch_bounds__(256, 2) void proj_gemm(
    const float* __restrict__ qsrc, const float* __restrict__ hsrc,
    const float* __restrict__ Wq,  const float* __restrict__ Wk,
    const float* __restrict__ Wv,  const float* __restrict__ W1,
    const float* __restrict__ W2,  const float* __restrict__ W3,
    const float* __restrict__ W4,  const float* __restrict__ W5,
    const float* __restrict__ W6)
{
    const int t = blockIdx.z;
    const bool half = (t >= 3);
    if (half && blockIdx.x >= MHALF / 128) return;
    const int nodeoff = (t >= 6) ? (1 + NPP) : 1;
    const int Mtot = half ? MHALF : MROWS;

    const float* src = (t == 0) ? qsrc : hsrc;
    const float* W;
    float* outp;
    switch (t) {
        case 0: W = Wq; outp = g_Q;  break;
        case 1: W = Wk; outp = g_K;  break;
        case 2: W = Wv; outp = g_V;  break;
        case 3: W = W1; outp = g_Q1; break;
        case 4: W = W2; outp = g_Q2; break;
        case 5: W = W3; outp = g_Q3; break;
        case 6: W = W4; outp = g_Q4; break;
        case 7: W = W5; outp = g_Q5; break;
        default: W = W6; outp = g_Q6; break;
    }

    __shared__ float Ash[16][132];
    __shared__ float Bsh[16][132];

    const int tid = threadIdx.x;
    const int m0 = blockIdx.x * 128;
    const int n0 = blockIdx.y * 128;
    const int cx = tid & 15;
    const int ry = tid >> 4;

    u64 acc2[8][4];
#pragma unroll
    for (int i = 0; i < 8; i++)
#pragma unroll
        for (int j = 0; j < 4; j++) acc2[i][j] = 0ull;

    for (int d0 = 0; d0 < 256; d0 += 16) {
#pragma unroll
        for (int i = 0; i < 2; i++) {
            int fid = tid + i * 256;
            int row = fid >> 2;
            int dg  = (fid & 3) * 4;
            int m   = m0 + row;
            float4 v = make_float4(0.f, 0.f, 0.f, 0.f);
            if (m < Mtot) {
                size_t srow = half
                    ? ((size_t)(m >> 8) * GG + nodeoff + (m & 255))
                    : (size_t)m;
                v = *(const float4*)(src + srow * 256 + d0 + dg);
            }
            Ash[dg + 0][row] = v.x;
            Ash[dg + 1][row] = v.y;
            Ash[dg + 2][row] = v.z;
            Ash[dg + 3][row] = v.w;
        }
#pragma unroll
        for (int i = 0; i < 2; i++) {
            int fid = tid + i * 256;
            int d   = fid >> 5;
            int nn  = (fid & 31) * 4;
            int n   = n0 + nn;
            float4 v = *(const float4*)(W + (size_t)(n >> 5) * 8192 +
                                        (size_t)(d0 + d) * 32 + (n & 31));
            *(float4*)&Bsh[d][nn] = v;
        }
        __syncthreads();

#pragma unroll
        for (int d = 0; d < 16; d++) {
            float4 a0 = *(const float4*)&Ash[d][ry * 4];
            float4 a1 = *(const float4*)&Ash[d][64 + ry * 4];
            ulonglong2 b0 = *(const ulonglong2*)&Bsh[d][cx * 4];
            ulonglong2 b1 = *(const ulonglong2*)&Bsh[d][64 + cx * 4];
            u64 bp[4] = {b0.x, b0.y, b1.x, b1.y};
            float ar[8] = {a0.x, a0.y, a0.z, a0.w, a1.x, a1.y, a1.z, a1.w};
#pragma unroll
            for (int i = 0; i < 8; i++) {
                u64 a2 = pk2(ar[i], ar[i]);
#pragma unroll
                for (int j = 0; j < 4; j++)
                    FMA2(acc2[i][j], a2, bp[j]);
            }
        }
        __syncthreads();
    }

#pragma unroll
    for (int i = 0; i < 8; i++) {
        int row = (i < 4) ? (ry * 4 + i) : (64 + ry * 4 + (i - 4));
        int m = m0 + row;
        if (m >= Mtot) continue;
        int bb, node;
        if (half) { bb = m >> 8; node = nodeoff + (m & 255); }
        else      { bb = m / GG; node = m % GG; }
        float accr[8];
#pragma unroll
        for (int j = 0; j < 4; j++) {
            float2 f = upk2(acc2[i][j]);
            accr[2 * j] = f.x; accr[2 * j + 1] = f.y;
        }
#pragma unroll
        for (int j = 0; j < 8; j++) {
            int n = n0 + ((j < 4) ? (cx * 4 + j) : (64 + cx * 4 + (j - 4)));
            int hh = n >> 5, kk = n & 31;
            outp[(((size_t)hh * BB + bb) * GG + node) * DKC + kk] = accr[j];
        }
    }
}

// ---------------------------------------------------------------------------
// Kernel B: fused attention, chunked-GEMM, 512 threads, f32x2 packed math.
// ---------------------------------------------------------------------------
__device__ __forceinline__ float warpMaxf(float v) {
#pragma unroll
    for (int o = 16; o; o >>= 1) v = fmaxf(v, __shfl_xor_sync(0xffffffffu, v, o));
    return v;
}
__device__ __forceinline__ float warpSumf(float v) {
#pragma unroll
    for (int o = 16; o; o >>= 1) v += __shfl_xor_sync(0xffffffffu, v, o);
    return v;
}

__global__ __launch_bounds__(512, 1) void attn_kernel()
{
    extern __shared__ float sm[];
    float* Kt  = sm + OFF_KT;
    float* Vt  = sm + OFF_VT;
    float* L0b = sm + OFF_L0;
    float* Lxb = sm + OFF_LX;

    const int b  = blockIdx.x;
    const int hh = blockIdx.y;
    const int tid = threadIdx.x, lane = tid & 31, wid = tid >> 5;
    const size_t base = (((size_t)hh * BB + b) * GG) * DKC;
    const float NINF = -CUDART_INF_F;

    if (tid < 96) {
        int k = tid / 3, cc = 513 + (tid - k * 3);
        Kt[k * PADM + cc] = 0.f;
        Vt[k * PADM + cc] = 0.f;
    }
    for (int i = tid; i < GG * DKC; i += 512) {
        int m = i >> 5, k = i & 31;
        Kt[k * PADM + m] = g_K[base + i];
        Vt[k * PADM + m] = g_V[base + i];
    }
    __syncthreads();

    for (int c = 0; c < 33; c++) {
        const int q0 = c * 16;

        // ---- Phase 1: stage query vectors ----
        for (int i = tid; i < 2048; i += 512) {
            int type = i >> 9, qq = (i >> 5) & 15, k = i & 31;
            int n = q0 + qq;
            float v = 0.f;
            if (n < GG) {
                size_t off = base + (size_t)n * 32 + k;
                bool pick = (n >= 1 && n <= NPP);
                if (type == 0)          v = g_Q[off];
                else if (n >= 1) {
                    if (type == 1)      v = pick ? g_Q2[off] : g_Q6[off];
                    else if (type == 2) v = pick ? g_Q3[off] : g_Q5[off];
                    else                v = pick ? g_Q1[off] : g_Q4[off];
                }
            }
            sm[OFF_QB + i] = v;
        }
        __syncthreads();

        // ---- Phase 2: logit GEMM (2q x 8keys, packed f32x2) ----
        {
            const int qg  = tid >> 6;
            const int qi0 = qg * 2;
            const int mt  = tid & 63;
            const int mA  = mt * 4;
            const int mB  = 256 + mt * 4;
            u64 L0p[2][4], Lxp[2][4];
#pragma unroll
            for (int q = 0; q < 2; q++)
#pragma unroll
                for (int j = 0; j < 4; j++) { L0p[q][j] = 0ull; Lxp[q][j] = 0ull; }

#pragma unroll
            for (int k4 = 0; k4 < 8; k4++) {
                float qv[2][4], u1[2][4], u2[2][4];
#pragma unroll
                for (int q = 0; q < 2; q++) {
                    *(float4*)qv[q] = *(const float4*)&sm[OFF_QB + (qi0 + q) * 32 + k4 * 4];
                    *(float4*)u1[q] = *(const float4*)&sm[OFF_U1 + (qi0 + q) * 32 + k4 * 4];
                    *(float4*)u2[q] = *(const float4*)&sm[OFF_U2 + (qi0 + q) * 32 + k4 * 4];
                }
#pragma unroll
                for (int kk = 0; kk < 4; kk++) {
                    int k = k4 * 4 + kk;
                    ulonglong2 ka = *(const ulonglong2*)&Kt[k * PADM + mA];
                    ulonglong2 kb = *(const ulonglong2*)&Kt[k * PADM + mB];
#pragma unroll
                    for (int q = 0; q < 2; q++) {
                        u64 qs2  = pk2(qv[q][kk], qv[q][kk]);
                        u64 u1s2 = pk2(u1[q][kk], u1[q][kk]);
                        u64 u2s2 = pk2(u2[q][kk], u2[q][kk]);
                        FMA2(L0p[q][0], qs2,  ka.x);
                        FMA2(L0p[q][1], qs2,  ka.y);
                        FMA2(L0p[q][2], qs2,  kb.x);
                        FMA2(L0p[q][3], qs2,  kb.y);
                        FMA2(Lxp[q][0], u1s2, ka.x);
                        FMA2(Lxp[q][1], u1s2, ka.y);
                        FMA2(Lxp[q][2], u2s2, kb.x);
                        FMA2(Lxp[q][3], u2s2, kb.y);
                    }
                }
            }
#pragma unroll
            for (int q = 0; q < 2; q++) {
                int qrow = qi0 + q;
                float2 p0 = upk2(L0p[q][0]), p1 = upk2(L0p[q][1]);
                float2 p2 = upk2(L0p[q][2]), p3 = upk2(L0p[q][3]);
                float4 oa = make_float4(p0.x*NORMC, p0.y*NORMC, p1.x*NORMC, p1.y*NORMC);
                float4 ob = make_float4(p2.x*NORMC, p2.y*NORMC, p3.x*NORMC, p3.y*NORMC);
                *(float4*)&L0b[qrow * LPAD + mA] = oa;
                *(float4*)&L0b[qrow * LPAD + mB] = ob;
                float2 x0 = upk2(Lxp[q][0]), x1 = upk2(Lxp[q][1]);
                float2 x2 = upk2(Lxp[q][2]), x3 = upk2(Lxp[q][3]);
                float4 xa = make_float4(x0.x*NORMC, x0.y*NORMC, x1.x*NORMC, x1.y*NORMC);
                float4 xb = make_float4(x2.x*NORMC, x2.y*NORMC, x3.x*NORMC, x3.y*NORMC);
                if (mt == 0) xa.x = NINF;   // m==0: no extra logit
                *(float4*)&Lxb[qrow * LPAD + mA] = xa;
                *(float4*)&Lxb[qrow * LPAD + mB] = xb;
            }
        }
        __syncthreads();

        // ---- Phase 3: softmax (warp per query) ----
        {
            int qq = wid;
            int n = q0 + qq;
            float* wrow = &L0b[qq * LPAD];
            float* xrow = &Lxb[qq * LPAD];
            if (n < GG) {
                const bool useX = (n >= 1);
                float kv512 = Kt[lane * PADM + 512];
                float l0_512 = NORMC * warpSumf(sm[OFF_QB + qq*32 + lane] * kv512);
                float lx512 = NINF, lp = NINF;
                int p = 0;
                if (useX) {
                    lx512 = NORMC * warpSumf(sm[OFF_U2 + qq*32 + lane] * kv512);
                    p = (n <= NPP) ? n + NPP : n - NPP;
                    float kvp = Kt[lane * PADM + p];
                    lp = NORMC * warpSumf(sm[OFF_QA + qq*32 + lane] * kvp);
                    // key 256 is a PICK key: extra logit uses u1, not u2
                    float kv256 = Kt[lane * PADM + 256];
                    float lx256 = NORMC * warpSumf(sm[OFF_U1 + qq*32 + lane] * kv256);
                    if (lane == 0) xrow[256] = lx256;
                    __syncwarp();
                }
                float mx = fmaxf(l0_512, fmaxf(lx512, lp));
#pragma unroll
                for (int i = 0; i < 4; i++) {
                    int m4 = i * 128 + lane * 4;
                    float4 a = *(const float4*)&wrow[m4];
                    mx = fmaxf(mx, fmaxf(fmaxf(a.x, a.y), fmaxf(a.z, a.w)));
                    if (useX) {
                        float4 x = *(const float4*)&xrow[m4];
                        mx = fmaxf(mx, fmaxf(fmaxf(x.x, x.y), fmaxf(x.z, x.w)));
                    }
                }
                mx = warpMaxf(mx);
                float tot = 0.f;
#pragma unroll
                for (int i = 0; i < 4; i++) {
                    int m4 = i * 128 + lane * 4;
                    float4 a = *(const float4*)&wrow[m4];
                    float4 wv;
                    wv.x = __expf(a.x - mx); wv.y = __expf(a.y - mx);
                    wv.z = __expf(a.z - mx); wv.w = __expf(a.w - mx);
                    if (useX) {
                        float4 x = *(const float4*)&xrow[m4];
                        wv.x += __expf(x.x - mx); wv.y += __expf(x.y - mx);
                        wv.z += __expf(x.z - mx); wv.w += __expf(x.w - mx);
                    }
                    tot += wv.x + wv.y + wv.z + wv.w;
                    *(float4*)&wrow[m4] = wv;
                }
                tot = warpSumf(tot);
                float w512 = __expf(l0_512 - mx) + (useX ? __expf(lx512 - mx) : 0.f);
                float wp   = useX ? __expf(lp - mx) : 0.f;
                tot += w512 + wp;
                __syncwarp();
                if (lane == 0) {
                    wrow[512] = w512;
                    if (useX) wrow[p] += wp;
                    wrow[513] = 0.f; wrow[514] = 0.f; wrow[515] = 0.f;
                    sm[OFF_TOT + qq] = 1.0f / tot;
                }
            } else {
                for (int i = lane; i < 129; i += 32)
                    *(float4*)&wrow[i * 4] = make_float4(0.f, 0.f, 0.f, 0.f);
                if (lane == 0) sm[OFF_TOT + qq] = 0.f;
            }
        }
        __syncthreads();

        // ---- Phase 4: AV GEMM (warp per 32-key slice, packed f32x2) ----
        {
            u64 acc2[16];
#pragma unroll
            for (int qq = 0; qq < 16; qq++) acc2[qq] = 0ull;
            const int iters = (wid == 15) ? 9 : 8;
            const int mbase = wid * 32;
            for (int it = 0; it < iters; it++) {
                int m4 = mbase + it * 4;
                ulonglong2 v2 = *(const ulonglong2*)&Vt[lane * PADM + m4];
#pragma unroll
                for (int qq = 0; qq < 16; qq++) {
                    ulonglong2 w2 = *(const ulonglong2*)&L0b[qq * LPAD + m4];
                    FMA2(acc2[qq], w2.x, v2.x);
                    FMA2(acc2[qq], w2.y, v2.y);
                }
            }
#pragma unroll
            for (int qq = 0; qq < 16; qq++) {
                float2 f = upk2(acc2[qq]);
                Lxb[(wid * 16 + qq) * 32 + lane] = f.x + f.y;
            }
        }
        __syncthreads();

        // ---- Phase 5: 16-way reduce + writeout ----
        {
            int qq = tid >> 5, k = tid & 31;
            float s = 0.f;
#pragma unroll
            for (int w = 0; w < 16; w++)
                s += Lxb[(w * 16 + qq) * 32 + k];
            int n = q0 + qq;
            if (n < GG)
                g_Hd[base + (size_t)n * 32 + k] = s * sm[OFF_TOT + qq];
        }
        __syncthreads();
    }
}

// ---------------------------------------------------------------------------
// Kernel C: output projection (f32x2 packed inner loop)
// ---------------------------------------------------------------------------
__global__ __launch_bounds__(256) void out_gemm(
    const float* __restrict__ Wout, float* __restrict__ out)
{
    __shared__ float Ash[16][132];
    __shared__ float Bsh[16][68];

    const int tid = threadIdx.x;
    const int m0 = blockIdx.x * 128;
    const int n0 = blockIdx.y * 64;
    const int cx = tid & 15;
    const int ry = tid >> 4;

    u64 acc2[8][2];
#pragma unroll
    for (int i = 0; i < 8; i++) { acc2[i][0] = 0ull; acc2[i][1] = 0ull; }

    for (int d0 = 0; d0 < 256; d0 += 16) {
#pragma unroll
        for (int i = 0; i < 2; i++) {
            int fid = tid + i * 256;
            int row = fid >> 2;
            int cg  = (fid & 3) * 4;
            int m   = m0 + row;
            int cc  = d0 + cg;
            float4 v = make_float4(0.f, 0.f, 0.f, 0.f);
            if (m < MROWS)
                v = *(const float4*)(g_Hd + (size_t)(cc >> 5) * MROWS * DKC +
                                     (size_t)m * DKC + (cc & 31));
            Ash[cg + 0][row] = v.x;
            Ash[cg + 1][row] = v.y;
            Ash[cg + 2][row] = v.z;
            Ash[cg + 3][row] = v.w;
        }
        {
            int d  = tid >> 4;
            int nn = (tid & 15) * 4;
            float4 v = *(const float4*)(Wout + (size_t)(d0 + d) * EE + n0 + nn);
            *(float4*)&Bsh[d][nn] = v;
        }
        __syncthreads();

#pragma unroll
        for (int d = 0; d < 16; d++) {
            float4 a0 = *(const float4*)&Ash[d][ry * 4];
            float4 a1 = *(const float4*)&Ash[d][64 + ry * 4];
            ulonglong2 bv = *(const ulonglong2*)&Bsh[d][cx * 4];
            float ar[8] = {a0.x, a0.y, a0.z, a0.w, a1.x, a1.y, a1.z, a1.w};
#pragma unroll
            for (int i = 0; i < 8; i++) {
                u64 a2 = pk2(ar[i], ar[i]);
                FMA2(acc2[i][0], a2, bv.x);
                FMA2(acc2[i][1], a2, bv.y);
            }
        }
        __syncthreads();
    }

#pragma unroll
    for (int i = 0; i < 8; i++) {
        int row = (i < 4) ? (ry * 4 + i) : (64 + ry * 4 + (i - 4));
        int m = m0 + row;
        if (m >= MROWS) continue;
        float2 f0 = upk2(acc2[i][0]);
        float2 f1 = upk2(acc2[i][1]);
        float accr[4] = {f0.x, f0.y, f1.x, f1.y};
#pragma unroll
        for (int j = 0; j < 4; j++) {
            out[(size_t)m * EE + n0 + cx * 4 + j] = accr[j];
        }
    }
}

// ---------------------------------------------------------------------------
extern "C" void kernel_launch(void* const* d_in, const int* in_sizes, int n_in,
                              void* d_out, int out_size)
{
    (void)in_sizes; (void)n_in; (void)out_size;
    const float* q    = (const float*)d_in[0];
    const float* h    = (const float*)d_in[1];
    const float* Wq   = (const float*)d_in[2];
    const float* Wk   = (const float*)d_in[3];
    const float* Wv   = (const float*)d_in[4];
    const float* W1   = (const float*)d_in[5];
    const float* W2   = (const float*)d_in[6];
    const float* W3   = (const float*)d_in[7];
    const float* W4   = (const float*)d_in[8];
    const float* W5   = (const float*)d_in[9];
    const float* W6   = (const float*)d_in[10];
    const float* Wout = (const float*)d_in[11];
    float* out = (float*)d_out;

    const int SMEM_ATTN = SMEM_FLOATS * (int)sizeof(float);  // 206912 B
    cudaFuncSetAttribute(attn_kernel,
                         cudaFuncAttributeMaxDynamicSharedMemorySize, SMEM_ATTN);

    dim3 gridP((MROWS + 127) / 128, 2, 9);
    proj_gemm<<<gridP, 256>>>(q, h, Wq, Wk, Wv, W1, W2, W3, W4, W5, W6);

    dim3 gridA(BB, HH);
    attn_kernel<<<gridA, 512, SMEM_ATTN>>>();

    dim3 gridO((MROWS + 127) / 128, 4);
    out_gemm<<<gridO, 256>>>(Wout, out);
}

// round 13
// speedup vs baseline: 1.7869x; 1.0899x over previous
#include <cuda_runtime.h>
#include <math_constants.h>

// Problem constants
#define HH   8
#define BB   16
#define GG   513
#define DD   256
#define DKC  32
#define EE   256
#define NPP  256
#define MROWS (BB*GG)            // 8208
#define MHALF (BB*NPP)           // 4096
#define PER  (HH*BB*GG*DKC)      // 2101248
#define NORMC 0.17677669529663687f

// attn smem layout (float offsets)
#define PADM 516
#define LPAD 520
#define OFF_KT  0
#define OFF_VT  16512
#define OFF_L0  33024
#define OFF_LX  41344
#define OFF_QB  49664
#define OFF_U1  50176
#define OFF_U2  50688
#define OFF_QA  51200
#define OFF_TOT 51712
#define SMEM_FLOATS 51728        // 206912 bytes

typedef unsigned long long u64;

// packed f32x2 helpers (Blackwell FFMA2 path)
__device__ __forceinline__ u64 pk2(float lo, float hi) {
    u64 r; asm("mov.b64 %0, {%1, %2};" : "=l"(r) : "f"(lo), "f"(hi)); return r;
}
__device__ __forceinline__ float2 upk2(u64 v) {
    float2 f; asm("mov.b64 {%0, %1}, %2;" : "=f"(f.x), "=f"(f.y) : "l"(v)); return f;
}
#define FMA2(d, a, b) asm("fma.rn.f32x2 %0, %1, %2, %0;" : "+l"(d) : "l"(a), "l"(b))

// Scratch (device globals; no allocation allowed)
__device__ float g_Q [PER];
__device__ float g_K [PER];
__device__ float g_V [PER];
__device__ float g_Q1[PER];
__device__ float g_Q2[PER];
__device__ float g_Q3[PER];
__device__ float g_Q4[PER];
__device__ float g_Q5[PER];
__device__ float g_Q6[PER];
__device__ float g_Hd[PER];

// ---------------------------------------------------------------------------
// Kernel A: projection GEMMs. 128x128 tile, 8x8 micro-tile (f32x2 packed),
// K-chunk 32 (8 iterations: half the LDG stall points / barriers).
// Targets 0..2: all rows; 3..5: pick rows only; 6..8: delivery rows only.
// ---------------------------------------------------------------------------
__global__ __launch_bounds__(256, 2) void proj_gemm(
    const float* __restrict__ qsrc, const float* __restrict__ hsrc,
    const float* __restrict__ Wq,  const float* __restrict__ Wk,
    const float* __restrict__ Wv,  const float* __restrict__ W1,
    const float* __restrict__ W2,  const float* __restrict__ W3,
    const float* __restrict__ W4,  const float* __restrict__ W5,
    const float* __restrict__ W6)
{
    const int t = blockIdx.z;
    const bool half = (t >= 3);
    if (half && blockIdx.x >= MHALF / 128) return;
    const int nodeoff = (t >= 6) ? (1 + NPP) : 1;
    const int Mtot = half ? MHALF : MROWS;

    const float* src = (t == 0) ? qsrc : hsrc;
    const float* W;
    float* outp;
    switch (t) {
        case 0: W = Wq; outp = g_Q;  break;
        case 1: W = Wk; outp = g_K;  break;
        case 2: W = Wv; outp = g_V;  break;
        case 3: W = W1; outp = g_Q1; break;
        case 4: W = W2; outp = g_Q2; break;
        case 5: W = W3; outp = g_Q3; break;
        case 6: W = W4; outp = g_Q4; break;
        case 7: W = W5; outp = g_Q5; break;
        default: W = W6; outp = g_Q6; break;
    }

    __shared__ float Ash[32][132];
    __shared__ float Bsh[32][132];

    const int tid = threadIdx.x;
    const int m0 = blockIdx.x * 128;
    const int n0 = blockIdx.y * 128;
    const int cx = tid & 15;
    const int ry = tid >> 4;

    u64 acc2[8][4];
#pragma unroll
    for (int i = 0; i < 8; i++)
#pragma unroll
        for (int j = 0; j < 4; j++) acc2[i][j] = 0ull;

    for (int d0 = 0; d0 < 256; d0 += 32) {
        // A tile: 128 rows x 32 d, transposed into Ash[d][row]
#pragma unroll
        for (int i = 0; i < 4; i++) {
            int fid = tid + i * 256;          // 0..1023
            int row = fid >> 3;               // 128 rows
            int dg  = (fid & 7) * 4;          // 32 d in groups of 4
            int m   = m0 + row;
            float4 v = make_float4(0.f, 0.f, 0.f, 0.f);
            if (m < Mtot) {
                size_t srow = half
                    ? ((size_t)(m >> 8) * GG + nodeoff + (m & 255))
                    : (size_t)m;
                v = *(const float4*)(src + srow * 256 + d0 + dg);
            }
            Ash[dg + 0][row] = v.x;
            Ash[dg + 1][row] = v.y;
            Ash[dg + 2][row] = v.z;
            Ash[dg + 3][row] = v.w;
        }
        // B tile: 32 d x 128 n (W is [h][d][k], n=h*32+k)
#pragma unroll
        for (int i = 0; i < 4; i++) {
            int fid = tid + i * 256;
            int d   = fid >> 5;               // 32 d
            int nn  = (fid & 31) * 4;         // 128 n
            int n   = n0 + nn;
            float4 v = *(const float4*)(W + (size_t)(n >> 5) * 8192 +
                                        (size_t)(d0 + d) * 32 + (n & 31));
            *(float4*)&Bsh[d][nn] = v;
        }
        __syncthreads();

#pragma unroll
        for (int d = 0; d < 32; d++) {
            float4 a0 = *(const float4*)&Ash[d][ry * 4];
            float4 a1 = *(const float4*)&Ash[d][64 + ry * 4];
            ulonglong2 b0 = *(const ulonglong2*)&Bsh[d][cx * 4];
            ulonglong2 b1 = *(const ulonglong2*)&Bsh[d][64 + cx * 4];
            u64 bp[4] = {b0.x, b0.y, b1.x, b1.y};
            float ar[8] = {a0.x, a0.y, a0.z, a0.w, a1.x, a1.y, a1.z, a1.w};
#pragma unroll
            for (int i = 0; i < 8; i++) {
                u64 a2 = pk2(ar[i], ar[i]);
#pragma unroll
                for (int j = 0; j < 4; j++)
                    FMA2(acc2[i][j], a2, bp[j]);
            }
        }
        __syncthreads();
    }

#pragma unroll
    for (int i = 0; i < 8; i++) {
        int row = (i < 4) ? (ry * 4 + i) : (64 + ry * 4 + (i - 4));
        int m = m0 + row;
        if (m >= Mtot) continue;
        int bb, node;
        if (half) { bb = m >> 8; node = nodeoff + (m & 255); }
        else      { bb = m / GG; node = m % GG; }
        float accr[8];
#pragma unroll
        for (int j = 0; j < 4; j++) {
            float2 f = upk2(acc2[i][j]);
            accr[2 * j] = f.x; accr[2 * j + 1] = f.y;
        }
#pragma unroll
        for (int j = 0; j < 8; j++) {
            int n = n0 + ((j < 4) ? (cx * 4 + j) : (64 + cx * 4 + (j - 4)));
            int hh = n >> 5, kk = n & 31;
            outp[(((size_t)hh * BB + bb) * GG + node) * DKC + kk] = accr[j];
        }
    }
}

// ---------------------------------------------------------------------------
// Kernel B: fused attention, chunked-GEMM, 512 threads, f32x2 packed math,
// register-prefetched P1, batched 4-wide special-logit reduction in P3.
// ---------------------------------------------------------------------------
__device__ __forceinline__ float warpMaxf(float v) {
#pragma unroll
    for (int o = 16; o; o >>= 1) v = fmaxf(v, __shfl_xor_sync(0xffffffffu, v, o));
    return v;
}
__device__ __forceinline__ float warpSumf(float v) {
#pragma unroll
    for (int o = 16; o; o >>= 1) v += __shfl_xor_sync(0xffffffffu, v, o);
    return v;
}

__global__ __launch_bounds__(512, 1) void attn_kernel()
{
    extern __shared__ float sm[];
    float* Kt  = sm + OFF_KT;
    float* Vt  = sm + OFF_VT;
    float* L0b = sm + OFF_L0;
    float* Lxb = sm + OFF_LX;

    const int b  = blockIdx.x;
    const int hh = blockIdx.y;
    const int tid = threadIdx.x, lane = tid & 31, wid = tid >> 5;
    const size_t base = (((size_t)hh * BB + b) * GG) * DKC;
    const float NINF = -CUDART_INF_F;

    // prefetch buffer for next chunk's staged q-vectors
    float pre[4];
    {
        // prefetch chunk 0 (overlaps the K/V smem fill below)
        const int q0 = 0;
#pragma unroll
        for (int s = 0; s < 4; s++) {
            int i = tid + s * 512;
            int type = i >> 9, qq = (i >> 5) & 15, k = i & 31;
            int n = q0 + qq;
            float v = 0.f;
            if (n < GG) {
                size_t off = base + (size_t)n * 32 + k;
                bool pick = (n >= 1 && n <= NPP);
                if (type == 0)          v = g_Q[off];
                else if (n >= 1) {
                    if (type == 1)      v = pick ? g_Q2[off] : g_Q6[off];
                    else if (type == 2) v = pick ? g_Q3[off] : g_Q5[off];
                    else                v = pick ? g_Q1[off] : g_Q4[off];
                }
            }
            pre[s] = v;
        }
    }

    if (tid < 96) {
        int k = tid / 3, cc = 513 + (tid - k * 3);
        Kt[k * PADM + cc] = 0.f;
        Vt[k * PADM + cc] = 0.f;
    }
    for (int i = tid; i < GG * DKC; i += 512) {
        int m = i >> 5, k = i & 31;
        Kt[k * PADM + m] = g_K[base + i];
        Vt[k * PADM + m] = g_V[base + i];
    }
    __syncthreads();

    for (int c = 0; c < 33; c++) {
        const int q0 = c * 16;

        // ---- Phase 1: commit prefetched q-vectors, start next prefetch ----
#pragma unroll
        for (int s = 0; s < 4; s++)
            sm[OFF_QB + tid + s * 512] = pre[s];
        __syncthreads();

        if (c + 1 < 33) {
            const int q1 = (c + 1) * 16;
#pragma unroll
            for (int s = 0; s < 4; s++) {
                int i = tid + s * 512;
                int type = i >> 9, qq = (i >> 5) & 15, k = i & 31;
                int n = q1 + qq;
                float v = 0.f;
                if (n < GG) {
                    size_t off = base + (size_t)n * 32 + k;
                    bool pick = (n >= 1 && n <= NPP);
                    if (type == 0)          v = g_Q[off];
                    else if (n >= 1) {
                        if (type == 1)      v = pick ? g_Q2[off] : g_Q6[off];
                        else if (type == 2) v = pick ? g_Q3[off] : g_Q5[off];
                        else                v = pick ? g_Q1[off] : g_Q4[off];
                    }
                }
                pre[s] = v;
            }
        }

        // ---- Phase 2: logit GEMM (2q x 8keys, packed f32x2) ----
        {
            const int qg  = tid >> 6;
            const int qi0 = qg * 2;
            const int mt  = tid & 63;
            const int mA  = mt * 4;
            const int mB  = 256 + mt * 4;
            u64 L0p[2][4], Lxp[2][4];
#pragma unroll
            for (int q = 0; q < 2; q++)
#pragma unroll
                for (int j = 0; j < 4; j++) { L0p[q][j] = 0ull; Lxp[q][j] = 0ull; }

#pragma unroll
            for (int k4 = 0; k4 < 8; k4++) {
                float qv[2][4], u1[2][4], u2[2][4];
#pragma unroll
                for (int q = 0; q < 2; q++) {
                    *(float4*)qv[q] = *(const float4*)&sm[OFF_QB + (qi0 + q) * 32 + k4 * 4];
                    *(float4*)u1[q] = *(const float4*)&sm[OFF_U1 + (qi0 + q) * 32 + k4 * 4];
                    *(float4*)u2[q] = *(const float4*)&sm[OFF_U2 + (qi0 + q) * 32 + k4 * 4];
                }
#pragma unroll
                for (int kk = 0; kk < 4; kk++) {
                    int k = k4 * 4 + kk;
                    ulonglong2 ka = *(const ulonglong2*)&Kt[k * PADM + mA];
                    ulonglong2 kb = *(const ulonglong2*)&Kt[k * PADM + mB];
#pragma unroll
                    for (int q = 0; q < 2; q++) {
                        u64 qs2  = pk2(qv[q][kk], qv[q][kk]);
                        u64 u1s2 = pk2(u1[q][kk], u1[q][kk]);
                        u64 u2s2 = pk2(u2[q][kk], u2[q][kk]);
                        FMA2(L0p[q][0], qs2,  ka.x);
                        FMA2(L0p[q][1], qs2,  ka.y);
                        FMA2(L0p[q][2], qs2,  kb.x);
                        FMA2(L0p[q][3], qs2,  kb.y);
                        FMA2(Lxp[q][0], u1s2, ka.x);
                        FMA2(Lxp[q][1], u1s2, ka.y);
                        FMA2(Lxp[q][2], u2s2, kb.x);
                        FMA2(Lxp[q][3], u2s2, kb.y);
                    }
                }
            }
#pragma unroll
            for (int q = 0; q < 2; q++) {
                int qrow = qi0 + q;
                float2 p0 = upk2(L0p[q][0]), p1 = upk2(L0p[q][1]);
                float2 p2 = upk2(L0p[q][2]), p3 = upk2(L0p[q][3]);
                float4 oa = make_float4(p0.x*NORMC, p0.y*NORMC, p1.x*NORMC, p1.y*NORMC);
                float4 ob = make_float4(p2.x*NORMC, p2.y*NORMC, p3.x*NORMC, p3.y*NORMC);
                *(float4*)&L0b[qrow * LPAD + mA] = oa;
                *(float4*)&L0b[qrow * LPAD + mB] = ob;
                float2 x0 = upk2(Lxp[q][0]), x1 = upk2(Lxp[q][1]);
                float2 x2 = upk2(Lxp[q][2]), x3 = upk2(Lxp[q][3]);
                float4 xa = make_float4(x0.x*NORMC, x0.y*NORMC, x1.x*NORMC, x1.y*NORMC);
                float4 xb = make_float4(x2.x*NORMC, x2.y*NORMC, x3.x*NORMC, x3.y*NORMC);
                if (mt == 0) xa.x = NINF;   // m==0: no extra logit
                *(float4*)&Lxb[qrow * LPAD + mA] = xa;
                *(float4*)&Lxb[qrow * LPAD + mB] = xb;
            }
        }
        __syncthreads();

        // ---- Phase 3: softmax (warp per query) ----
        {
            int qq = wid;
            int n = q0 + qq;
            float* wrow = &L0b[qq * LPAD];
            float* xrow = &Lxb[qq * LPAD];
            if (n < GG) {
                const bool useX = (n >= 1);
                // batched 4-wide special-logit reduction:
                //   x: key-512 base   y: key-512 extra   z: pair   w: key-256 u1-fix
                float kv512 = Kt[lane * PADM + 512];
                float4 sp;
                sp.x = sm[OFF_QB + qq*32 + lane] * kv512;
                sp.y = 0.f; sp.z = 0.f; sp.w = 0.f;
                int p = 0;
                if (useX) {
                    sp.y = sm[OFF_U2 + qq*32 + lane] * kv512;
                    p = (n <= NPP) ? n + NPP : n - NPP;
                    sp.z = sm[OFF_QA + qq*32 + lane] * Kt[lane * PADM + p];
                    sp.w = sm[OFF_U1 + qq*32 + lane] * Kt[lane * PADM + 256];
                }
#pragma unroll
                for (int o = 16; o; o >>= 1) {
                    sp.x += __shfl_xor_sync(0xffffffffu, sp.x, o);
                    sp.y += __shfl_xor_sync(0xffffffffu, sp.y, o);
                    sp.z += __shfl_xor_sync(0xffffffffu, sp.z, o);
                    sp.w += __shfl_xor_sync(0xffffffffu, sp.w, o);
                }
                float l0_512 = NORMC * sp.x;
                float lx512 = useX ? NORMC * sp.y : NINF;
                float lp    = useX ? NORMC * sp.z : NINF;
                if (useX) {
                    if (lane == 0) xrow[256] = NORMC * sp.w;  // key-256 uses u1
                    __syncwarp();
                }
                float mx = fmaxf(l0_512, fmaxf(lx512, lp));
#pragma unroll
                for (int i = 0; i < 4; i++) {
                    int m4 = i * 128 + lane * 4;
                    float4 a = *(const float4*)&wrow[m4];
                    mx = fmaxf(mx, fmaxf(fmaxf(a.x, a.y), fmaxf(a.z, a.w)));
                    if (useX) {
                        float4 x = *(const float4*)&xrow[m4];
                        mx = fmaxf(mx, fmaxf(fmaxf(x.x, x.y), fmaxf(x.z, x.w)));
                    }
                }
                mx = warpMaxf(mx);
                float tot = 0.f;
#pragma unroll
                for (int i = 0; i < 4; i++) {
                    int m4 = i * 128 + lane * 4;
                    float4 a = *(const float4*)&wrow[m4];
                    float4 wv;
                    wv.x = __expf(a.x - mx); wv.y = __expf(a.y - mx);
                    wv.z = __expf(a.z - mx); wv.w = __expf(a.w - mx);
                    if (useX) {
                        float4 x = *(const float4*)&xrow[m4];
                        wv.x += __expf(x.x - mx); wv.y += __expf(x.y - mx);
                        wv.z += __expf(x.z - mx); wv.w += __expf(x.w - mx);
                    }
                    tot += wv.x + wv.y + wv.z + wv.w;
                    *(float4*)&wrow[m4] = wv;
                }
                tot = warpSumf(tot);
                float w512 = __expf(l0_512 - mx) + (useX ? __expf(lx512 - mx) : 0.f);
                float wp   = useX ? __expf(lp - mx) : 0.f;
                tot += w512 + wp;
                __syncwarp();
                if (lane == 0) {
                    wrow[512] = w512;
                    if (useX) wrow[p] += wp;
                    wrow[513] = 0.f; wrow[514] = 0.f; wrow[515] = 0.f;
                    sm[OFF_TOT + qq] = 1.0f / tot;
                }
            } else {
                for (int i = lane; i < 129; i += 32)
                    *(float4*)&wrow[i * 4] = make_float4(0.f, 0.f, 0.f, 0.f);
                if (lane == 0) sm[OFF_TOT + qq] = 0.f;
            }
        }
        __syncthreads();

        // ---- Phase 4: AV GEMM (warp per 32-key slice, packed f32x2) ----
        {
            u64 acc2[16];
#pragma unroll
            for (int qq = 0; qq < 16; qq++) acc2[qq] = 0ull;
            const int iters = (wid == 15) ? 9 : 8;
            const int mbase = wid * 32;
            for (int it = 0; it < iters; it++) {
                int m4 = mbase + it * 4;
                ulonglong2 v2 = *(const ulonglong2*)&Vt[lane * PADM + m4];
#pragma unroll
                for (int qq = 0; qq < 16; qq++) {
                    ulonglong2 w2 = *(const ulonglong2*)&L0b[qq * LPAD + m4];
                    FMA2(acc2[qq], w2.x, v2.x);
                    FMA2(acc2[qq], w2.y, v2.y);
                }
            }
#pragma unroll
            for (int qq = 0; qq < 16; qq++) {
                float2 f = upk2(acc2[qq]);
                Lxb[(wid * 16 + qq) * 32 + lane] = f.x + f.y;
            }
        }
        __syncthreads();

        // ---- Phase 5: 16-way reduce + writeout ----
        {
            int qq = tid >> 5, k = tid & 31;
            float s = 0.f;
#pragma unroll
            for (int w = 0; w < 16; w++)
                s += Lxb[(w * 16 + qq) * 32 + k];
            int n = q0 + qq;
            if (n < GG)
                g_Hd[base + (size_t)n * 32 + k] = s * sm[OFF_TOT + qq];
        }
        __syncthreads();
    }
}

// ---------------------------------------------------------------------------
// Kernel C: output projection (f32x2 packed inner loop)
// ---------------------------------------------------------------------------
__global__ __launch_bounds__(256) void out_gemm(
    const float* __restrict__ Wout, float* __restrict__ out)
{
    __shared__ float Ash[16][132];
    __shared__ float Bsh[16][68];

    const int tid = threadIdx.x;
    const int m0 = blockIdx.x * 128;
    const int n0 = blockIdx.y * 64;
    const int cx = tid & 15;
    const int ry = tid >> 4;

    u64 acc2[8][2];
#pragma unroll
    for (int i = 0; i < 8; i++) { acc2[i][0] = 0ull; acc2[i][1] = 0ull; }

    for (int d0 = 0; d0 < 256; d0 += 16) {
#pragma unroll
        for (int i = 0; i < 2; i++) {
            int fid = tid + i * 256;
            int row = fid >> 2;
            int cg  = (fid & 3) * 4;
            int m   = m0 + row;
            int cc  = d0 + cg;
            float4 v = make_float4(0.f, 0.f, 0.f, 0.f);
            if (m < MROWS)
                v = *(const float4*)(g_Hd + (size_t)(cc >> 5) * MROWS * DKC +
                                     (size_t)m * DKC + (cc & 31));
            Ash[cg + 0][row] = v.x;
            Ash[cg + 1][row] = v.y;
            Ash[cg + 2][row] = v.z;
            Ash[cg + 3][row] = v.w;
        }
        {
            int d  = tid >> 4;
            int nn = (tid & 15) * 4;
            float4 v = *(const float4*)(Wout + (size_t)(d0 + d) * EE + n0 + nn);
            *(float4*)&Bsh[d][nn] = v;
        }
        __syncthreads();

#pragma unroll
        for (int d = 0; d < 16; d++) {
            float4 a0 = *(const float4*)&Ash[d][ry * 4];
            float4 a1 = *(const float4*)&Ash[d][64 + ry * 4];
            ulonglong2 bv = *(const ulonglong2*)&Bsh[d][cx * 4];
            float ar[8] = {a0.x, a0.y, a0.z, a0.w, a1.x, a1.y, a1.z, a1.w};
#pragma unroll
            for (int i = 0; i < 8; i++) {
                u64 a2 = pk2(ar[i], ar[i]);
                FMA2(acc2[i][0], a2, bv.x);
                FMA2(acc2[i][1], a2, bv.y);
            }
        }
        __syncthreads();
    }

#pragma unroll
    for (int i = 0; i < 8; i++) {
        int row = (i < 4) ? (ry * 4 + i) : (64 + ry * 4 + (i - 4));
        int m = m0 + row;
        if (m >= MROWS) continue;
        float2 f0 = upk2(acc2[i][0]);
        float2 f1 = upk2(acc2[i][1]);
        float accr[4] = {f0.x, f0.y, f1.x, f1.y};
#pragma unroll
        for (int j = 0; j < 4; j++) {
            out[(size_t)m * EE + n0 + cx * 4 + j] = accr[j];
        }
    }
}

// ---------------------------------------------------------------------------
extern "C" void kernel_launch(void* const* d_in, const int* in_sizes, int n_in,
                              void* d_out, int out_size)
{
    (void)in_sizes; (void)n_in; (void)out_size;
    const float* q    = (const float*)d_in[0];
    const float* h    = (const float*)d_in[1];
    const float* Wq   = (const float*)d_in[2];
    const float* Wk   = (const float*)d_in[3];
    const float* Wv   = (const float*)d_in[4];
    const float* W1   = (const float*)d_in[5];
    const float* W2   = (const float*)d_in[6];
    const float* W3   = (const float*)d_in[7];
    const float* W4   = (const float*)d_in[8];
    const float* W5   = (const float*)d_in[9];
    const float* W6   = (const float*)d_in[10];
    const float* Wout = (const float*)d_in[11];
    float* out = (float*)d_out;

    const int SMEM_ATTN = SMEM_FLOATS * (int)sizeof(float);  // 206912 B
    cudaFuncSetAttribute(attn_kernel,
                         cudaFuncAttributeMaxDynamicSharedMemorySize, SMEM_ATTN);

    dim3 gridP((MROWS + 127) / 128, 2, 9);
    proj_gemm<<<gridP, 256>>>(q, h, Wq, Wk, Wv, W1, W2, W3, W4, W5, W6);

    dim3 gridA(BB, HH);
    attn_kernel<<<gridA, 512, SMEM_ATTN>>>();

    dim3 gridO((MROWS + 127) / 128, 4);
    out_gemm<<<gridO, 256>>>(Wout, out);
}

// round 15
// speedup vs baseline: 1.8609x; 1.0414x over previous
#include <cuda_runtime.h>
#include <math_constants.h>

// Problem constants
#define HH   8
#define BB   16
#define GG   513
#define DD   256
#define DKC  32
#define EE   256
#define NPP  256
#define MROWS (BB*GG)            // 8208
#define MHALF (BB*NPP)           // 4096
#define PER  (HH*BB*GG*DKC)      // 2101248
#define NORMC 0.17677669529663687f
#define SCL  (NORMC * 1.4426950408889634f)   // NORMC * log2(e): logits pre-scaled for ex2

// attn smem layout (float offsets)
#define PADM 516
#define LPAD 520
#define OFF_KT  0
#define OFF_VT  16512
#define OFF_L0  33024
#define OFF_LX  41344
#define OFF_QB  49664
#define OFF_U1  50176
#define OFF_U2  50688
#define OFF_QA  51200
#define OFF_TOT 51712
#define SMEM_FLOATS 51728        // 206912 bytes

typedef unsigned long long u64;

// packed f32x2 helpers (Blackwell FFMA2 path)
__device__ __forceinline__ u64 pk2(float lo, float hi) {
    u64 r; asm("mov.b64 %0, {%1, %2};" : "=l"(r) : "f"(lo), "f"(hi)); return r;
}
__device__ __forceinline__ float2 upk2(u64 v) {
    float2 f; asm("mov.b64 {%0, %1}, %2;" : "=f"(f.x), "=f"(f.y) : "l"(v)); return f;
}
#define FMA2(d, a, b) asm("fma.rn.f32x2 %0, %1, %2, %0;" : "+l"(d) : "l"(a), "l"(b))

__device__ __forceinline__ float ex2(float x) {
    float r; asm("ex2.approx.ftz.f32 %0, %1;" : "=f"(r) : "f"(x)); return r;
}

// Scratch (device globals; no allocation allowed)
__device__ float g_Q [PER];
__device__ float g_K [PER];
__device__ float g_V [PER];
__device__ float g_Q1[PER];
__device__ float g_Q2[PER];
__device__ float g_Q3[PER];
__device__ float g_Q4[PER];
__device__ float g_Q5[PER];
__device__ float g_Q6[PER];
__device__ float g_Hd[PER];

// ---------------------------------------------------------------------------
// Kernel A: projection GEMMs. 128x128 tile, 8x8 micro-tile (f32x2 packed),
// K-chunk 16 (best measured), FLATTENED 1D grid of exactly 774 working CTAs:
//   [0,390): full targets 0..2 (130 CTAs each = 65 mtiles x 2 ntiles)
//   [390,774): half targets 3..8 (64 CTAs each = 32 mtiles x 2 ntiles)
// ---------------------------------------------------------------------------
__global__ __launch_bounds__(256, 2) void proj_gemm(
    const float* __restrict__ qsrc, const float* __restrict__ hsrc,
    const float* __restrict__ Wq,  const float* __restrict__ Wk,
    const float* __restrict__ Wv,  const float* __restrict__ W1,
    const float* __restrict__ W2,  const float* __restrict__ W3,
    const float* __restrict__ W4,  const float* __restrict__ W5,
    const float* __restrict__ W6)
{
    const int bx = blockIdx.x;
    int t, mtile, ntile;
    if (bx < 390) {
        t = bx / 130;
        int r = bx % 130;
        ntile = r / 65;
        mtile = r % 65;
    } else {
        int r = bx - 390;
        t = 3 + (r >> 6);
        int rr = r & 63;
        ntile = rr >> 5;
        mtile = rr & 31;
    }
    const bool half = (t >= 3);
    const int nodeoff = (t >= 6) ? (1 + NPP) : 1;
    const int Mtot = half ? MHALF : MROWS;

    const float* src = (t == 0) ? qsrc : hsrc;
    const float* W;
    float* outp;
    switch (t) {
        case 0: W = Wq; outp = g_Q;  break;
        case 1: W = Wk; outp = g_K;  break;
        case 2: W = Wv; outp = g_V;  break;
        case 3: W = W1; outp = g_Q1; break;
        case 4: W = W2; outp = g_Q2; break;
        case 5: W = W3; outp = g_Q3; break;
        case 6: W = W4; outp = g_Q4; break;
        case 7: W = W5; outp = g_Q5; break;
        default: W = W6; outp = g_Q6; break;
    }

    __shared__ float Ash[16][132];
    __shared__ float Bsh[16][132];

    const int tid = threadIdx.x;
    const int m0 = mtile * 128;
    const int n0 = ntile * 128;
    const int cx = tid & 15;
    const int ry = tid >> 4;

    u64 acc2[8][4];
#pragma unroll
    for (int i = 0; i < 8; i++)
#pragma unroll
        for (int j = 0; j < 4; j++) acc2[i][j] = 0ull;

    for (int d0 = 0; d0 < 256; d0 += 16) {
#pragma unroll
        for (int i = 0; i < 2; i++) {
            int fid = tid + i * 256;
            int row = fid >> 2;
            int dg  = (fid & 3) * 4;
            int m   = m0 + row;
            float4 v = make_float4(0.f, 0.f, 0.f, 0.f);
            if (m < Mtot) {
                size_t srow = half
                    ? ((size_t)(m >> 8) * GG + nodeoff + (m & 255))
                    : (size_t)m;
                v = *(const float4*)(src + srow * 256 + d0 + dg);
            }
            Ash[dg + 0][row] = v.x;
            Ash[dg + 1][row] = v.y;
            Ash[dg + 2][row] = v.z;
            Ash[dg + 3][row] = v.w;
        }
#pragma unroll
        for (int i = 0; i < 2; i++) {
            int fid = tid + i * 256;
            int d   = fid >> 5;
            int nn  = (fid & 31) * 4;
            int n   = n0 + nn;
            float4 v = *(const float4*)(W + (size_t)(n >> 5) * 8192 +
                                        (size_t)(d0 + d) * 32 + (n & 31));
            *(float4*)&Bsh[d][nn] = v;
        }
        __syncthreads();

#pragma unroll
        for (int d = 0; d < 16; d++) {
            float4 a0 = *(const float4*)&Ash[d][ry * 4];
            float4 a1 = *(const float4*)&Ash[d][64 + ry * 4];
            ulonglong2 b0 = *(const ulonglong2*)&Bsh[d][cx * 4];
            ulonglong2 b1 = *(const ulonglong2*)&Bsh[d][64 + cx * 4];
            u64 bp[4] = {b0.x, b0.y, b1.x, b1.y};
            float ar[8] = {a0.x, a0.y, a0.z, a0.w, a1.x, a1.y, a1.z, a1.w};
#pragma unroll
            for (int i = 0; i < 8; i++) {
                u64 a2 = pk2(ar[i], ar[i]);
#pragma unroll
                for (int j = 0; j < 4; j++)
                    FMA2(acc2[i][j], a2, bp[j]);
            }
        }
        __syncthreads();
    }

#pragma unroll
    for (int i = 0; i < 8; i++) {
        int row = (i < 4) ? (ry * 4 + i) : (64 + ry * 4 + (i - 4));
        int m = m0 + row;
        if (m >= Mtot) continue;
        int bb, node;
        if (half) { bb = m >> 8; node = nodeoff + (m & 255); }
        else      { bb = m / GG; node = m % GG; }
        float accr[8];
#pragma unroll
        for (int j = 0; j < 4; j++) {
            float2 f = upk2(acc2[i][j]);
            accr[2 * j] = f.x; accr[2 * j + 1] = f.y;
        }
#pragma unroll
        for (int j = 0; j < 8; j++) {
            int n = n0 + ((j < 4) ? (cx * 4 + j) : (64 + cx * 4 + (j - 4)));
            int hh = n >> 5, kk = n & 31;
            outp[(((size_t)hh * BB + bb) * GG + node) * DKC + kk] = accr[j];
        }
    }
}

// ---------------------------------------------------------------------------
// Kernel B: fused attention, chunked-GEMM, 512 threads, f32x2 packed math,
// prefetched staging, NO softmax max-subtraction (ex2 on pre-scaled logits),
// P1-commit merged into P5 (4 barriers/chunk).
// ---------------------------------------------------------------------------
__device__ __forceinline__ float warpSumf(float v) {
#pragma unroll
    for (int o = 16; o; o >>= 1) v += __shfl_xor_sync(0xffffffffu, v, o);
    return v;
}

__global__ __launch_bounds__(512, 1) void attn_kernel()
{
    extern __shared__ float sm[];
    float* Kt  = sm + OFF_KT;
    float* Vt  = sm + OFF_VT;
    float* L0b = sm + OFF_L0;
    float* Lxb = sm + OFF_LX;

    const int b  = blockIdx.x;
    const int hh = blockIdx.y;
    const int tid = threadIdx.x, lane = tid & 31, wid = tid >> 5;
    const size_t base = (((size_t)hh * BB + b) * GG) * DKC;
    const float NINF = -CUDART_INF_F;

    // prefetch chunk 0's staged q-vectors (overlaps K/V smem fill)
    float nxt[4];
#pragma unroll
    for (int s = 0; s < 4; s++) {
        int i = tid + s * 512;
        int type = i >> 9, qq = (i >> 5) & 15, k = i & 31;
        int n = qq;                      // chunk 0: q0 = 0
        float v = 0.f;
        if (n < GG) {
            size_t off = base + (size_t)n * 32 + k;
            bool pick = (n >= 1 && n <= NPP);
            if (type == 0)          v = g_Q[off];
            else if (n >= 1) {
                if (type == 1)      v = pick ? g_Q2[off] : g_Q6[off];
                else if (type == 2) v = pick ? g_Q3[off] : g_Q5[off];
                else                v = pick ? g_Q1[off] : g_Q4[off];
            }
        }
        nxt[s] = v;
    }

    if (tid < 96) {
        int k = tid / 3, cc = 513 + (tid - k * 3);
        Kt[k * PADM + cc] = 0.f;
        Vt[k * PADM + cc] = 0.f;
    }
    for (int i = tid; i < GG * DKC; i += 512) {
        int m = i >> 5, k = i & 31;
        Kt[k * PADM + m] = g_K[base + i];
        Vt[k * PADM + m] = g_V[base + i];
    }
    // commit chunk 0 staging
#pragma unroll
    for (int s = 0; s < 4; s++)
        sm[OFF_QB + tid + s * 512] = nxt[s];
    __syncthreads();

    for (int c = 0; c < 33; c++) {
        const int q0 = c * 16;

        // prefetch chunk c+1 (registers; no barrier)
        if (c + 1 < 33) {
            const int q1 = (c + 1) * 16;
#pragma unroll
            for (int s = 0; s < 4; s++) {
                int i = tid + s * 512;
                int type = i >> 9, qq = (i >> 5) & 15, k = i & 31;
                int n = q1 + qq;
                float v = 0.f;
                if (n < GG) {
                    size_t off = base + (size_t)n * 32 + k;
                    bool pick = (n >= 1 && n <= NPP);
                    if (type == 0)          v = g_Q[off];
                    else if (n >= 1) {
                        if (type == 1)      v = pick ? g_Q2[off] : g_Q6[off];
                        else if (type == 2) v = pick ? g_Q3[off] : g_Q5[off];
                        else                v = pick ? g_Q1[off] : g_Q4[off];
                    }
                }
                nxt[s] = v;
            }
        }

        // ---- Phase 2: logit GEMM (2q x 8keys, packed f32x2), SCL pre-scale ----
        {
            const int qg  = tid >> 6;
            const int qi0 = qg * 2;
            const int mt  = tid & 63;
            const int mA  = mt * 4;
            const int mB  = 256 + mt * 4;
            u64 L0p[2][4], Lxp[2][4];
#pragma unroll
            for (int q = 0; q < 2; q++)
#pragma unroll
                for (int j = 0; j < 4; j++) { L0p[q][j] = 0ull; Lxp[q][j] = 0ull; }

#pragma unroll
            for (int k4 = 0; k4 < 8; k4++) {
                float qv[2][4], u1[2][4], u2[2][4];
#pragma unroll
                for (int q = 0; q < 2; q++) {
                    *(float4*)qv[q] = *(const float4*)&sm[OFF_QB + (qi0 + q) * 32 + k4 * 4];
                    *(float4*)u1[q] = *(const float4*)&sm[OFF_U1 + (qi0 + q) * 32 + k4 * 4];
                    *(float4*)u2[q] = *(const float4*)&sm[OFF_U2 + (qi0 + q) * 32 + k4 * 4];
                }
#pragma unroll
                for (int kk = 0; kk < 4; kk++) {
                    int k = k4 * 4 + kk;
                    ulonglong2 ka = *(const ulonglong2*)&Kt[k * PADM + mA];
                    ulonglong2 kb = *(const ulonglong2*)&Kt[k * PADM + mB];
#pragma unroll
                    for (int q = 0; q < 2; q++) {
                        u64 qs2  = pk2(qv[q][kk], qv[q][kk]);
                        u64 u1s2 = pk2(u1[q][kk], u1[q][kk]);
                        u64 u2s2 = pk2(u2[q][kk], u2[q][kk]);
                        FMA2(L0p[q][0], qs2,  ka.x);
                        FMA2(L0p[q][1], qs2,  ka.y);
                        FMA2(L0p[q][2], qs2,  kb.x);
                        FMA2(L0p[q][3], qs2,  kb.y);
                        FMA2(Lxp[q][0], u1s2, ka.x);
                        FMA2(Lxp[q][1], u1s2, ka.y);
                        FMA2(Lxp[q][2], u2s2, kb.x);
                        FMA2(Lxp[q][3], u2s2, kb.y);
                    }
                }
            }
#pragma unroll
            for (int q = 0; q < 2; q++) {
                int qrow = qi0 + q;
                float2 p0 = upk2(L0p[q][0]), p1 = upk2(L0p[q][1]);
                float2 p2 = upk2(L0p[q][2]), p3 = upk2(L0p[q][3]);
                float4 oa = make_float4(p0.x*SCL, p0.y*SCL, p1.x*SCL, p1.y*SCL);
                float4 ob = make_float4(p2.x*SCL, p2.y*SCL, p3.x*SCL, p3.y*SCL);
                *(float4*)&L0b[qrow * LPAD + mA] = oa;
                *(float4*)&L0b[qrow * LPAD + mB] = ob;
                float2 x0 = upk2(Lxp[q][0]), x1 = upk2(Lxp[q][1]);
                float2 x2 = upk2(Lxp[q][2]), x3 = upk2(Lxp[q][3]);
                float4 xa = make_float4(x0.x*SCL, x0.y*SCL, x1.x*SCL, x1.y*SCL);
                float4 xb = make_float4(x2.x*SCL, x2.y*SCL, x3.x*SCL, x3.y*SCL);
                if (mt == 0) xa.x = NINF;   // m==0: no extra logit
                *(float4*)&Lxb[qrow * LPAD + mA] = xa;
                *(float4*)&Lxb[qrow * LPAD + mB] = xb;
            }
        }
        __syncthreads();

        // ---- Phase 3: softmax, NO max-subtraction (logits bounded) ----
        {
            int qq = wid;
            int n = q0 + qq;
            float* wrow = &L0b[qq * LPAD];
            float* xrow = &Lxb[qq * LPAD];
            if (n < GG) {
                const bool useX = (n >= 1);
                // batched 4-wide special-logit reduction:
                //   x: key-512 base   y: key-512 extra   z: pair   w: key-256 u1-fix
                float kv512 = Kt[lane * PADM + 512];
                float4 sp;
                sp.x = sm[OFF_QB + qq*32 + lane] * kv512;
                sp.y = 0.f; sp.z = 0.f; sp.w = 0.f;
                int p = 0;
                if (useX) {
                    sp.y = sm[OFF_U2 + qq*32 + lane] * kv512;
                    p = (n <= NPP) ? n + NPP : n - NPP;
                    sp.z = sm[OFF_QA + qq*32 + lane] * Kt[lane * PADM + p];
                    sp.w = sm[OFF_U1 + qq*32 + lane] * Kt[lane * PADM + 256];
                }
#pragma unroll
                for (int o = 16; o; o >>= 1) {
                    sp.x += __shfl_xor_sync(0xffffffffu, sp.x, o);
                    sp.y += __shfl_xor_sync(0xffffffffu, sp.y, o);
                    sp.z += __shfl_xor_sync(0xffffffffu, sp.z, o);
                    sp.w += __shfl_xor_sync(0xffffffffu, sp.w, o);
                }
                if (useX) {
                    if (lane == 0) xrow[256] = SCL * sp.w;  // key-256 uses u1
                    __syncwarp();
                }
                float tot = 0.f;
#pragma unroll
                for (int i = 0; i < 4; i++) {
                    int m4 = i * 128 + lane * 4;
                    float4 a = *(const float4*)&wrow[m4];
                    float4 wv;
                    wv.x = ex2(a.x); wv.y = ex2(a.y);
                    wv.z = ex2(a.z); wv.w = ex2(a.w);
                    if (useX) {
                        float4 x = *(const float4*)&xrow[m4];
                        wv.x += ex2(x.x); wv.y += ex2(x.y);
                        wv.z += ex2(x.z); wv.w += ex2(x.w);
                    }
                    tot += wv.x + wv.y + wv.z + wv.w;
                    *(float4*)&wrow[m4] = wv;
                }
                tot = warpSumf(tot);
                float w512 = ex2(SCL * sp.x) + (useX ? ex2(SCL * sp.y) : 0.f);
                float wp   = useX ? ex2(SCL * sp.z) : 0.f;
                tot += w512 + wp;
                __syncwarp();
                if (lane == 0) {
                    wrow[512] = w512;
                    if (useX) wrow[p] += wp;
                    wrow[513] = 0.f; wrow[514] = 0.f; wrow[515] = 0.f;
                    sm[OFF_TOT + qq] = 1.0f / tot;
                }
            } else {
                for (int i = lane; i < 129; i += 32)
                    *(float4*)&wrow[i * 4] = make_float4(0.f, 0.f, 0.f, 0.f);
                if (lane == 0) sm[OFF_TOT + qq] = 0.f;
            }
        }
        __syncthreads();

        // ---- Phase 4: AV GEMM (warp per 32-key slice, packed f32x2) ----
        {
            u64 acc2[16];
#pragma unroll
            for (int qq = 0; qq < 16; qq++) acc2[qq] = 0ull;
            const int iters = (wid == 15) ? 9 : 8;
            const int mbase = wid * 32;
            for (int it = 0; it < iters; it++) {
                int m4 = mbase + it * 4;
                ulonglong2 v2 = *(const ulonglong2*)&Vt[lane * PADM + m4];
#pragma unroll
                for (int qq = 0; qq < 16; qq++) {
                    ulonglong2 w2 = *(const ulonglong2*)&L0b[qq * LPAD + m4];
                    FMA2(acc2[qq], w2.x, v2.x);
                    FMA2(acc2[qq], w2.y, v2.y);
                }
            }
#pragma unroll
            for (int qq = 0; qq < 16; qq++) {
                float2 f = upk2(acc2[qq]);
                Lxb[(wid * 16 + qq) * 32 + lane] = f.x + f.y;
            }
        }
        __syncthreads();

        // ---- Phase 5: 16-way reduce + writeout + commit next chunk staging ----
        {
            int qq = tid >> 5, k = tid & 31;
            float s = 0.f;
#pragma unroll
            for (int w = 0; w < 16; w++)
                s += Lxb[(w * 16 + qq) * 32 + k];
            int n = q0 + qq;
            if (n < GG)
                g_Hd[base + (size_t)n * 32 + k] = s * sm[OFF_TOT + qq];
        }
        if (c + 1 < 33) {
#pragma unroll
            for (int s = 0; s < 4; s++)
                sm[OFF_QB + tid + s * 512] = nxt[s];
        }
        __syncthreads();
    }
}

// ---------------------------------------------------------------------------
// Kernel C: output projection (f32x2 packed inner loop)
// ---------------------------------------------------------------------------
__global__ __launch_bounds__(256) void out_gemm(
    const float* __restrict__ Wout, float* __restrict__ out)
{
    __shared__ float Ash[16][132];
    __shared__ float Bsh[16][68];

    const int tid = threadIdx.x;
    const int m0 = blockIdx.x * 128;
    const int n0 = blockIdx.y * 64;
    const int cx = tid & 15;
    const int ry = tid >> 4;

    u64 acc2[8][2];
#pragma unroll
    for (int i = 0; i < 8; i++) { acc2[i][0] = 0ull; acc2[i][1] = 0ull; }

    for (int d0 = 0; d0 < 256; d0 += 16) {
#pragma unroll
        for (int i = 0; i < 2; i++) {
            int fid = tid + i * 256;
            int row = fid >> 2;
            int cg  = (fid & 3) * 4;
            int m   = m0 + row;
            int cc  = d0 + cg;
            float4 v = make_float4(0.f, 0.f, 0.f, 0.f);
            if (m < MROWS)
                v = *(const float4*)(g_Hd + (size_t)(cc >> 5) * MROWS * DKC +
                                     (size_t)m * DKC + (cc & 31));
            Ash[cg + 0][row] = v.x;
            Ash[cg + 1][row] = v.y;
            Ash[cg + 2][row] = v.z;
            Ash[cg + 3][row] = v.w;
        }
        {
            int d  = tid >> 4;
            int nn = (tid & 15) * 4;
            float4 v = *(const float4*)(Wout + (size_t)(d0 + d) * EE + n0 + nn);
            *(float4*)&Bsh[d][nn] = v;
        }
        __syncthreads();

#pragma unroll
        for (int d = 0; d < 16; d++) {
            float4 a0 = *(const float4*)&Ash[d][ry * 4];
            float4 a1 = *(const float4*)&Ash[d][64 + ry * 4];
            ulonglong2 bv = *(const ulonglong2*)&Bsh[d][cx * 4];
            float ar[8] = {a0.x, a0.y, a0.z, a0.w, a1.x, a1.y, a1.z, a1.w};
#pragma unroll
            for (int i = 0; i < 8; i++) {
                u64 a2 = pk2(ar[i], ar[i]);
                FMA2(acc2[i][0], a2, bv.x);
                FMA2(acc2[i][1], a2, bv.y);
            }
        }
        __syncthreads();
    }

#pragma unroll
    for (int i = 0; i < 8; i++) {
        int row = (i < 4) ? (ry * 4 + i) : (64 + ry * 4 + (i - 4));
        int m = m0 + row;
        if (m >= MROWS) continue;
        float2 f0 = upk2(acc2[i][0]);
        float2 f1 = upk2(acc2[i][1]);
        float accr[4] = {f0.x, f0.y, f1.x, f1.y};
#pragma unroll
        for (int j = 0; j < 4; j++) {
            out[(size_t)m * EE + n0 + cx * 4 + j] = accr[j];
        }
    }
}

// ---------------------------------------------------------------------------
extern "C" void kernel_launch(void* const* d_in, const int* in_sizes, int n_in,
                              void* d_out, int out_size)
{
    (void)in_sizes; (void)n_in; (void)out_size;
    const float* q    = (const float*)d_in[0];
    const float* h    = (const float*)d_in[1];
    const float* Wq   = (const float*)d_in[2];
    const float* Wk   = (const float*)d_in[3];
    const float* Wv   = (const float*)d_in[4];
    const float* W1   = (const float*)d_in[5];
    const float* W2   = (const float*)d_in[6];
    const float* W3   = (const float*)d_in[7];
    const float* W4   = (const float*)d_in[8];
    const float* W5   = (const float*)d_in[9];
    const float* W6   = (const float*)d_in[10];
    const float* Wout = (const float*)d_in[11];
    float* out = (float*)d_out;

    const int SMEM_ATTN = SMEM_FLOATS * (int)sizeof(float);  // 206912 B
    cudaFuncSetAttribute(attn_kernel,
                         cudaFuncAttributeMaxDynamicSharedMemorySize, SMEM_ATTN);

    proj_gemm<<<774, 256>>>(q, h, Wq, Wk, Wv, W1, W2, W3, W4, W5, W6);

    dim3 gridA(BB, HH);
    attn_kernel<<<gridA, 512, SMEM_ATTN>>>();

    dim3 gridO((MROWS + 127) / 128, 4);
    out_gemm<<<gridO, 256>>>(Wout, out);
}